// round 3
// baseline (speedup 1.0000x reference)
#include <cuda_runtime.h>

// ---------------- problem constants ----------------
#define BU 8
#define NTOK 320            // v*w = 5*64

// scratch (global device arrays; allocation-free per harness rules)
__device__ float g_X [8*40*5*64*64];   // attention+Wc output, conv1-input layout [b][c8*5+v][ar][h][w]
__device__ float g_Y1[8*64*5*64*64];   // conv1 output [b][c][ar][h][w]

// ---------------- attention kernel smem layout (floats) ----------------
#define PS_STRIDE 324
#define SM_QKV   (64*PS_STRIDE)          // 20736  (region 0: Bs[64][320] then P[64][324])
#define SM_W     (SM_QKV + 56*320)       // 38656
#define SM_RINV  (SM_W + 64*96)          // 44800
#define ATTN_SMEM_FLOATS (SM_RINV + 64)  // 44864
#define ATTN_SMEM_BYTES  (ATTN_SMEM_FLOATS*4)

__global__ __launch_bounds__(512)
void attn_kernel(const float* __restrict__ buffer,
                 const float* __restrict__ Wq, const float* __restrict__ Wk,
                 const float* __restrict__ Wv, const float* __restrict__ Wc)
{
    extern __shared__ float sm[];
    float* Bs   = sm;             // [64][320], c-major, n = v*64+w
    float* Ps   = sm;             // [64][PS_STRIDE], overlays Bs after phase A
    float* QKV  = sm + SM_QKV;    // rows 0-7 Q, 8-15 K, 16-55 V ; [56][320]
    float* Wsm  = sm + SM_W;      // [c][96]  (oc: 0-7 Wq, 8-15 Wk, 16-55 Wv, 56-95 Wc)
    float* rinv = sm + SM_RINV;   // [64] per-row 1/sum for current tile

    const int h    = blockIdx.x;
    const int b    = blockIdx.y;
    const int t    = threadIdx.x;
    const int lane = t & 31;
    const int wid  = t >> 5;      // 16 warps

    // ---- load weights to smem (transposed, broadcast-friendly) ----
    for (int idx = t; idx < 96*64; idx += 512) {
        int oc = idx >> 6, c = idx & 63;
        float v;
        if      (oc <  8) v = Wq[(oc      )*64 + c];
        else if (oc < 16) v = Wk[(oc -  8)*64 + c];
        else if (oc < 56) v = Wv[(oc - 16)*64 + c];
        else              v = Wc[(oc - 56)*64 + c];
        Wsm[c*96 + oc] = v;
    }
    // ---- load buffer slice Bs[c][v*64+w] (float4, coalesced) ----
    for (int f = t; f < 5120; f += 512) {
        int r  = f >> 4;          // c*5 + v
        int w4 = f & 15;
        int c = r / 5, v = r % 5;
        float4 val = *(const float4*)(buffer + (((size_t)(b*64 + c)*5 + v)*4096 + h*64 + w4*4));
        *(float4*)(Bs + c*320 + v*64 + w4*4) = val;
    }
    __syncthreads();

    // ---- Phase A: [96 x 64] x [64 x 320]: Q,K,V to smem, Wc-out to g_X ----
    {
        const int ocb = wid * 6;              // 16 warps * 6 oc = 96
        float acc[6][10];
        #pragma unroll
        for (int i = 0; i < 6; i++)
            #pragma unroll
            for (int j = 0; j < 10; j++) acc[i][j] = 0.f;

        for (int c = 0; c < 64; c++) {
            float wr[6];
            #pragma unroll
            for (int i = 0; i < 6; i++) wr[i] = Wsm[c*96 + ocb + i];
            #pragma unroll
            for (int j = 0; j < 10; j++) {
                float bv = Bs[c*320 + lane + 32*j];
                #pragma unroll
                for (int i = 0; i < 6; i++) acc[i][j] += wr[i]*bv;
            }
        }
        #pragma unroll
        for (int i = 0; i < 6; i++) {
            int oc = ocb + i;
            #pragma unroll
            for (int j = 0; j < 10; j++) {
                int n = lane + 32*j;
                if (oc < 56) {
                    QKV[oc*320 + n] = acc[i][j];
                } else {
                    int cc = oc - 56;                    // attention out-channel = c8*5 + ar
                    int c8 = cc / 5, ar = cc % 5;
                    int v = n >> 6, w = n & 63;
                    g_X[((((size_t)b*40 + c8*5 + v)*5 + ar)*64 + h)*64 + w] = acc[i][j];
                }
            }
        }
    }
    __syncthreads();

    // ---- Phase B: 5 tiles of 64 rows ----
    for (int tile = 0; tile < 5; tile++) {
        const int m0 = tile * 64;

        // B1: scores (inner dim 8) + softmax -> Ps (unnormalized exp), rinv
        {
            float q[4][8];
            #pragma unroll
            for (int mi = 0; mi < 4; mi++)
                #pragma unroll
                for (int d = 0; d < 8; d++)
                    q[mi][d] = QKV[d*320 + m0 + wid*4 + mi];

            float s[4][10];
            #pragma unroll
            for (int j = 0; j < 10; j++) {
                int n = lane + 32*j;
                float kv[8];
                #pragma unroll
                for (int d = 0; d < 8; d++) kv[d] = QKV[(8+d)*320 + n];
                #pragma unroll
                for (int mi = 0; mi < 4; mi++) {
                    float a = 0.f;
                    #pragma unroll
                    for (int d = 0; d < 8; d++) a += q[mi][d]*kv[d];
                    s[mi][j] = a;
                }
            }
            #pragma unroll
            for (int mi = 0; mi < 4; mi++) {
                float mx = s[mi][0];
                #pragma unroll
                for (int j = 1; j < 10; j++) mx = fmaxf(mx, s[mi][j]);
                #pragma unroll
                for (int o = 16; o; o >>= 1) mx = fmaxf(mx, __shfl_xor_sync(0xffffffffu, mx, o));
                float sum = 0.f;
                #pragma unroll
                for (int j = 0; j < 10; j++) { float e = __expf(s[mi][j] - mx); s[mi][j] = e; sum += e; }
                #pragma unroll
                for (int o = 16; o; o >>= 1) sum += __shfl_xor_sync(0xffffffffu, sum, o);
                int r = wid*4 + mi;
                #pragma unroll
                for (int j = 0; j < 10; j++) Ps[r*PS_STRIDE + lane + 32*j] = s[mi][j];
                if (lane == 0) rinv[r] = 1.0f / sum;
            }
        }
        __syncthreads();

        // B2: O[64][40] = P[64][320] * V^T ; subgroup of 8 lanes per row
        {
            const int sg = lane >> 3, l8 = lane & 7;
            const int r  = wid*4 + sg;          // tile-local row
            float acc[40];
            #pragma unroll
            for (int oc = 0; oc < 40; oc++) acc[oc] = 0.f;

            const float* prow = Ps + r*PS_STRIDE;
            const float* vbase = QKV + 16*320;
            for (int jj = 0; jj < 40; jj++) {
                int n = jj*8 + l8;
                float p = prow[n];
                const float* vp = vbase + n;
                #pragma unroll
                for (int oc = 0; oc < 40; oc++) acc[oc] += p * vp[oc*320];
            }
            #pragma unroll
            for (int oc = 0; oc < 40; oc++) {
                float a = acc[oc];
                a += __shfl_xor_sync(0xffffffffu, a, 1);
                a += __shfl_xor_sync(0xffffffffu, a, 2);
                a += __shfl_xor_sync(0xffffffffu, a, 4);
                acc[oc] = a;
            }
            float scale = rinv[r];
            int m_g = m0 + r;
            int v = m_g >> 6, w = m_g & 63;
            // lane l8 writes oc = l8*5 + q2  ->  c8 = l8, ar = q2
            #pragma unroll
            for (int q2 = 0; q2 < 5; q2++) {
                int oc = l8*5 + q2;
                size_t idx = ((((size_t)b*40 + l8*5 + v)*5 + q2)*64 + h)*64 + w;
                g_X[idx] += scale * acc[oc];
            }
        }
        __syncthreads();
    }
}

// ---------------- conv1: [64oc] x [40ci x 7kw] over W, + ReLU ----------------
#define C1_WS_OFF 2880                       // Xs[40][72]
#define C1_SMEM_FLOATS (C1_WS_OFF + 280*65)  // 21080
#define C1_SMEM_BYTES  (C1_SMEM_FLOATS*4)

__global__ __launch_bounds__(256)
void conv1_kernel(const float* __restrict__ W1)
{
    extern __shared__ float sm[];
    float* Xs = sm;               // [ci][72], data at [ci][3+w], pads zeroed
    float* Ws = sm + C1_WS_OFF;   // [(ci*7+kw)*65 + oc]
    const int h = blockIdx.x, d = blockIdx.y, b = blockIdx.z;
    const int t = threadIdx.x, lane = t & 31;
    const int ocb = (t >> 5) * 8;

    // zero pad columns only (indices 0..2 and 64+3..64+5 -> 67..69)
    for (int idx = t; idx < 240; idx += 256) {
        int ci = idx / 6, p = idx % 6;
        Xs[ci*72 + (p < 3 ? p : 64 + p)] = 0.f;
    }
    // fill X rows
    for (int idx = t; idx < 40*64; idx += 256) {
        int ci = idx >> 6, w = idx & 63;
        Xs[ci*72 + 3 + w] = g_X[(((size_t)b*40 + ci)*5 + d)*4096 + h*64 + w];
    }
    // weights: LDG-coalesced, STS conflict-free (stride 65)
    for (int idx = t; idx < 64*280; idx += 256) {
        int oc = idx / 280, r = idx % 280;
        Ws[r*65 + oc] = W1[idx];
    }
    __syncthreads();

    float acc0[8], acc1[8];
    #pragma unroll
    for (int i = 0; i < 8; i++) { acc0[i] = 0.f; acc1[i] = 0.f; }

    for (int ci = 0; ci < 40; ci++) {
        #pragma unroll
        for (int kw = 0; kw < 7; kw++) {
            float x0 = Xs[ci*72 + lane + kw];
            float x1 = Xs[ci*72 + 32 + lane + kw];
            const float* wp = Ws + (ci*7+kw)*65 + ocb;
            #pragma unroll
            for (int i = 0; i < 8; i++) { float wv = wp[i]; acc0[i] += wv*x0; acc1[i] += wv*x1; }
        }
    }
    size_t obase = (((size_t)b*64 + ocb)*5 + d)*4096 + h*64;
    #pragma unroll
    for (int i = 0; i < 8; i++) {
        g_Y1[obase + (size_t)i*5*4096 + lane]      = fmaxf(acc0[i], 0.f);
        g_Y1[obase + (size_t)i*5*4096 + 32 + lane] = fmaxf(acc1[i], 0.f);
    }
}

// ---------------- conv2: [64oc] x [64c x 7kd] over D(=5), + ReLU ----------------
#define C2_WS_OFF 20480                       // Ys[64][5][64]
#define C2_SMEM_FLOATS (C2_WS_OFF + 448*65)   // 49600
#define C2_SMEM_BYTES  (C2_SMEM_FLOATS*4)

__global__ __launch_bounds__(512)
void conv2_kernel(const float* __restrict__ W2, float* __restrict__ out)
{
    extern __shared__ float sm[];
    float* Ys = sm;               // [(c*5+d)*64 + w]
    float* Ws = sm + C2_WS_OFF;   // [(c*7+kd)*65 + oc]
    const int h = blockIdx.x, b = blockIdx.y;
    const int t = threadIdx.x;
    const int oc = t >> 3, wg = t & 7;

    for (int f = t; f < 5120; f += 512) {
        int r = f >> 4, w4 = f & 15;
        int c = r / 5, d = r % 5;
        *(float4*)(Ys + r*64 + w4*4) =
            *(const float4*)(g_Y1 + (((size_t)b*64 + c)*5 + d)*4096 + h*64 + w4*4);
    }
    for (int idx = t; idx < 64*448; idx += 512) {
        int o = idx / 448, r = idx % 448;
        Ws[r*65 + o] = W2[idx];
    }
    __syncthreads();

    float acc[5][8];
    #pragma unroll
    for (int d = 0; d < 5; d++)
        #pragma unroll
        for (int j = 0; j < 8; j++) acc[d][j] = 0.f;

    for (int c = 0; c < 64; c++) {
        float wr[7];
        #pragma unroll
        for (int kd = 0; kd < 7; kd++) wr[kd] = Ws[(c*7+kd)*65 + oc];
        #pragma unroll
        for (int dp = 0; dp < 5; dp++) {
            const float* yp = Ys + (c*5+dp)*64 + wg*8;
            float4 ya = *(const float4*)yp;
            float4 yb = *(const float4*)(yp + 4);
            float y[8] = {ya.x, ya.y, ya.z, ya.w, yb.x, yb.y, yb.z, yb.w};
            #pragma unroll
            for (int d = 0; d < 5; d++) {
                int kd = dp - d + 3;
                if (kd < 0 || kd > 6) continue;     // compile-time pruned
                float wv = wr[kd];
                #pragma unroll
                for (int j = 0; j < 8; j++) acc[d][j] += wv*y[j];
            }
        }
    }
    #pragma unroll
    for (int d = 0; d < 5; d++) {
        size_t idx = (((size_t)b*64 + oc)*5 + d)*4096 + h*64 + wg*8;
        float4 o0, o1;
        o0.x = fmaxf(acc[d][0], 0.f); o0.y = fmaxf(acc[d][1], 0.f);
        o0.z = fmaxf(acc[d][2], 0.f); o0.w = fmaxf(acc[d][3], 0.f);
        o1.x = fmaxf(acc[d][4], 0.f); o1.y = fmaxf(acc[d][5], 0.f);
        o1.z = fmaxf(acc[d][6], 0.f); o1.w = fmaxf(acc[d][7], 0.f);
        *(float4*)(out + idx)     = o0;
        *(float4*)(out + idx + 4) = o1;
    }
}

// ---------------- launch ----------------
extern "C" void kernel_launch(void* const* d_in, const int* in_sizes, int n_in,
                              void* d_out, int out_size)
{
    const float* buffer = (const float*)d_in[0];
    const float* Wq = (const float*)d_in[1];
    const float* Wk = (const float*)d_in[2];
    const float* Wv = (const float*)d_in[3];
    const float* Wc = (const float*)d_in[4];
    const float* W1 = (const float*)d_in[5];
    const float* W2 = (const float*)d_in[6];
    float* out = (float*)d_out;

    cudaFuncSetAttribute(attn_kernel,  cudaFuncAttributeMaxDynamicSharedMemorySize, ATTN_SMEM_BYTES);
    cudaFuncSetAttribute(conv1_kernel, cudaFuncAttributeMaxDynamicSharedMemorySize, C1_SMEM_BYTES);
    cudaFuncSetAttribute(conv2_kernel, cudaFuncAttributeMaxDynamicSharedMemorySize, C2_SMEM_BYTES);

    attn_kernel <<<dim3(64, 8),    512, ATTN_SMEM_BYTES>>>(buffer, Wq, Wk, Wv, Wc);
    conv1_kernel<<<dim3(64, 5, 8), 256, C1_SMEM_BYTES>>>(W1);
    conv2_kernel<<<dim3(64, 8),    512, C2_SMEM_BYTES>>>(W2, out);
}

// round 4
// speedup vs baseline: 1.0482x; 1.0482x over previous
#include <cuda_runtime.h>

typedef unsigned long long ULL;

// ---------------- f32x2 helpers ----------------
__device__ __forceinline__ ULL pk2(float lo, float hi) {
    ULL r; asm("mov.b64 %0, {%1, %2};" : "=l"(r) : "f"(lo), "f"(hi)); return r;
}
__device__ __forceinline__ void upk2(ULL v, float& lo, float& hi) {
    asm("mov.b64 {%0, %1}, %2;" : "=f"(lo), "=f"(hi) : "l"(v));
}
__device__ __forceinline__ ULL ffma2(ULL a, ULL b, ULL c) {
    ULL d; asm("fma.rn.f32x2 %0, %1, %2, %3;" : "=l"(d) : "l"(a), "l"(b), "l"(c));
    return d;
}
__device__ __forceinline__ int remap(int n) { return (n / 40) * 42 + (n % 40); }

// ---------------- scratch ----------------
__device__ float g_X [8*40*5*64*64];   // [b][c8*5+v][ar][h][w]
__device__ float g_Y1[8*64*5*64*64];   // [b][c][ar][h][w]

// ---------------- attn smem layout (floats) ----------------
#define PSS 336                 // P row stride (8 chunks * 42)
#define QKS 336                 // Q/K row stride (chunked layout)
#define VSS 368                 // V row stride (bank-engineered: 5*368 % 32 == 16)
#define SM_PS   0               // Ps[64][336] = 21504 ; Bs[64][320] = 20480 overlays
#define SM_Q    21504           // Qs[8][336]
#define SM_K    24192           // Ks[8][336]
#define SM_V    26880           // Vs[40][368] = 14720
#define SM_W    41600           // Wsm[64][96]
#define SM_RINV 47744           // [64]
#define ATTN_SMEM_FLOATS 47808
#define ATTN_SMEM_BYTES  (ATTN_SMEM_FLOATS*4)

__global__ __launch_bounds__(512)
void attn_kernel(const float* __restrict__ buffer,
                 const float* __restrict__ Wq, const float* __restrict__ Wk,
                 const float* __restrict__ Wv, const float* __restrict__ Wc)
{
    extern __shared__ float sm[];
    float* Bs   = sm;            // [64][320] (Phase A input), later overlaid by Ps
    float* Wsm  = sm + SM_W;     // [c][96]
    float* rinv = sm + SM_RINV;

    const int h    = blockIdx.x;
    const int b    = blockIdx.y;
    const int t    = threadIdx.x;
    const int lane = t & 31;
    const int wid  = t >> 5;     // 16 warps

    // ---- weights -> smem (transposed) ----
    for (int idx = t; idx < 96*64; idx += 512) {
        int oc = idx >> 6, c = idx & 63;
        float v;
        if      (oc <  8) v = Wq[(oc      )*64 + c];
        else if (oc < 16) v = Wk[(oc -  8)*64 + c];
        else if (oc < 56) v = Wv[(oc - 16)*64 + c];
        else              v = Wc[(oc - 56)*64 + c];
        Wsm[c*96 + oc] = v;
    }
    // ---- buffer slice Bs[c][v*64+w] ----
    for (int f = t; f < 5120; f += 512) {
        int r  = f >> 4;
        int w4 = f & 15;
        int c = r / 5, v = r % 5;
        float4 val = *(const float4*)(buffer + (((size_t)(b*64 + c)*5 + v)*4096 + h*64 + w4*4));
        *(float4*)(Bs + c*320 + v*64 + w4*4) = val;
    }
    __syncthreads();

    // ---- Phase A: [96oc x 64c] x [64c x 320n], packed over n-pairs ----
    {
        const int ocb = wid * 6;
        ULL acc[6][5];
        #pragma unroll
        for (int i = 0; i < 6; i++)
            #pragma unroll
            for (int jp = 0; jp < 5; jp++) acc[i][jp] = 0ull;

        for (int c = 0; c < 64; c++) {
            ULL w2[6];
            #pragma unroll
            for (int i = 0; i < 6; i++) { float wv = Wsm[c*96 + ocb + i]; w2[i] = pk2(wv, wv); }
            #pragma unroll
            for (int jp = 0; jp < 5; jp++) {
                ULL b2 = *(const ULL*)(Bs + c*320 + 2*lane + 64*jp);
                #pragma unroll
                for (int i = 0; i < 6; i++) acc[i][jp] = ffma2(w2[i], b2, acc[i][jp]);
            }
        }
        #pragma unroll
        for (int i = 0; i < 6; i++) {
            int oc = ocb + i;
            #pragma unroll
            for (int jp = 0; jp < 5; jp++) {
                int n  = 2*lane + 64*jp;      // even, pairs never straddle a 40-chunk
                int rn = remap(n);
                if (oc < 8)       *(ULL*)(sm + SM_Q + oc*QKS + rn)       = acc[i][jp];
                else if (oc < 16) *(ULL*)(sm + SM_K + (oc-8)*QKS + rn)   = acc[i][jp];
                else if (oc < 56) *(ULL*)(sm + SM_V + (oc-16)*VSS + rn)  = acc[i][jp];
                else {
                    int cc = oc - 56;          // c8*5 + ar
                    int c8 = cc / 5, ar = cc % 5;
                    int v = jp, w = 2*lane;
                    float lo, hi; upk2(acc[i][jp], lo, hi);
                    size_t idx = ((((size_t)b*40 + c8*5 + v)*5 + ar)*64 + h)*64 + w;
                    *(float2*)(g_X + idx) = make_float2(lo, hi);
                }
            }
        }
    }
    __syncthreads();

    // ---- Phase B: 5 tiles of 64 rows ----
    for (int tile = 0; tile < 5; tile++) {
        const int m0 = tile * 64;

        // B1: scores + softmax -> Ps (unnormalized exp, chunked layout), rinv
        {
            ULL q2[4][8];
            #pragma unroll
            for (int mi = 0; mi < 4; mi++) {
                int rm = remap(m0 + wid*4 + mi);
                #pragma unroll
                for (int d = 0; d < 8; d++) {
                    float qq = sm[SM_Q + d*QKS + rm];
                    q2[mi][d] = pk2(qq, qq);
                }
            }
            ULL s2[4][5];
            #pragma unroll
            for (int jp = 0; jp < 5; jp++) {
                int off = remap(2*lane + 64*jp);
                ULL kv2[8];
                #pragma unroll
                for (int d = 0; d < 8; d++) kv2[d] = *(const ULL*)(sm + SM_K + d*QKS + off);
                #pragma unroll
                for (int mi = 0; mi < 4; mi++) {
                    ULL a = 0ull;
                    #pragma unroll
                    for (int d = 0; d < 8; d++) a = ffma2(q2[mi][d], kv2[d], a);
                    s2[mi][jp] = a;
                }
            }
            #pragma unroll
            for (int mi = 0; mi < 4; mi++) {
                float mx = -1e30f;
                #pragma unroll
                for (int jp = 0; jp < 5; jp++) {
                    float lo, hi; upk2(s2[mi][jp], lo, hi);
                    mx = fmaxf(mx, fmaxf(lo, hi));
                }
                #pragma unroll
                for (int o = 16; o; o >>= 1) mx = fmaxf(mx, __shfl_xor_sync(0xffffffffu, mx, o));
                float sum = 0.f;
                int r = wid*4 + mi;
                #pragma unroll
                for (int jp = 0; jp < 5; jp++) {
                    float lo, hi; upk2(s2[mi][jp], lo, hi);
                    lo = __expf(lo - mx); hi = __expf(hi - mx);
                    sum += lo + hi;
                    int off = remap(2*lane + 64*jp);
                    *(ULL*)(sm + SM_PS + r*PSS + off) = pk2(lo, hi);
                }
                #pragma unroll
                for (int o = 16; o; o >>= 1) sum += __shfl_xor_sync(0xffffffffu, sum, o);
                if (lane == 0) rinv[r] = 1.0f / sum;
            }
        }
        __syncthreads();

        // B2: O[64][40] = P[64][320] * V^T  (8 rows x 5 ocs per thread, n split 8)
        {
            const int rowgrp = wid & 7;
            const int ocgrp  = (wid >> 3)*4 + (lane >> 3);
            const int l8     = lane & 7;

            ULL acc[8][5];
            #pragma unroll
            for (int ri = 0; ri < 8; ri++)
                #pragma unroll
                for (int i = 0; i < 5; i++) acc[ri][i] = 0ull;

            const float* pbase = sm + SM_PS + (rowgrp*8)*PSS + l8*42;
            const float* vbase = sm + SM_V  + (ocgrp*5)*VSS + l8*42;

            for (int j = 0; j < 20; j++) {
                ULL p2[8];
                #pragma unroll
                for (int ri = 0; ri < 8; ri++) p2[ri] = *(const ULL*)(pbase + ri*PSS + 2*j);
                #pragma unroll
                for (int i = 0; i < 5; i++) {
                    ULL v2 = *(const ULL*)(vbase + i*VSS + 2*j);
                    #pragma unroll
                    for (int ri = 0; ri < 8; ri++) acc[ri][i] = ffma2(p2[ri], v2, acc[ri][i]);
                }
            }

            float red[8][5];
            #pragma unroll
            for (int ri = 0; ri < 8; ri++)
                #pragma unroll
                for (int i = 0; i < 5; i++) {
                    float lo, hi; upk2(acc[ri][i], lo, hi);
                    float a = lo + hi;
                    a += __shfl_xor_sync(0xffffffffu, a, 1);
                    a += __shfl_xor_sync(0xffffffffu, a, 2);
                    a += __shfl_xor_sync(0xffffffffu, a, 4);
                    red[ri][i] = a;
                }
            #pragma unroll
            for (int ri = 0; ri < 8; ri++) {
                if (l8 == ri) {
                    int r = rowgrp*8 + ri;
                    int m = m0 + r;
                    int v = m >> 6, w = m & 63;
                    float scale = rinv[r];
                    #pragma unroll
                    for (int i = 0; i < 5; i++) {
                        size_t idx = ((((size_t)b*40 + ocgrp*5 + v)*5 + i)*64 + h)*64 + w;
                        g_X[idx] += scale * red[ri][i];
                    }
                }
            }
        }
        __syncthreads();
    }
}

// ---------------- conv1: [64oc] x [40ci x 7kw] over W, + ReLU (oc-pair packed) ----------------
#define C1_WS_OFF 2880                       // Xs[40][72]
#define C1_SMEM_FLOATS (C1_WS_OFF + 280*66)  // Ws stride 66 for aligned oc-pair LDS.64
#define C1_SMEM_BYTES  (C1_SMEM_FLOATS*4)

__global__ __launch_bounds__(256)
void conv1_kernel(const float* __restrict__ W1)
{
    extern __shared__ float sm[];
    float* Xs = sm;               // [ci][72], data at [ci][3+w]
    float* Ws = sm + C1_WS_OFF;   // [(ci*7+kw)*66 + oc]
    const int h = blockIdx.x, d = blockIdx.y, b = blockIdx.z;
    const int t = threadIdx.x, lane = t & 31;
    const int ocb = (t >> 5) * 8;

    for (int idx = t; idx < 240; idx += 256) {
        int ci = idx / 6, p = idx % 6;
        Xs[ci*72 + (p < 3 ? p : 64 + p)] = 0.f;
    }
    for (int idx = t; idx < 40*64; idx += 256) {
        int ci = idx >> 6, w = idx & 63;
        Xs[ci*72 + 3 + w] = g_X[(((size_t)b*40 + ci)*5 + d)*4096 + h*64 + w];
    }
    for (int idx = t; idx < 64*280; idx += 256) {
        int oc = idx / 280, r = idx % 280;
        Ws[r*66 + oc] = W1[idx];
    }
    __syncthreads();

    ULL acc[4][2];
    #pragma unroll
    for (int i = 0; i < 4; i++) { acc[i][0] = 0ull; acc[i][1] = 0ull; }

    for (int ci = 0; ci < 40; ci++) {
        #pragma unroll
        for (int kw = 0; kw < 7; kw++) {
            float x0 = Xs[ci*72 + lane + kw];
            float x1 = Xs[ci*72 + 32 + lane + kw];
            ULL xx0 = pk2(x0, x0), xx1 = pk2(x1, x1);
            const float* wp = Ws + (ci*7+kw)*66 + ocb;
            #pragma unroll
            for (int i = 0; i < 4; i++) {
                ULL w2 = *(const ULL*)(wp + 2*i);
                acc[i][0] = ffma2(w2, xx0, acc[i][0]);
                acc[i][1] = ffma2(w2, xx1, acc[i][1]);
            }
        }
    }
    size_t obase = (((size_t)b*64 + ocb)*5 + d)*4096 + h*64;
    #pragma unroll
    for (int i = 0; i < 4; i++) {
        float a0lo, a0hi, a1lo, a1hi;
        upk2(acc[i][0], a0lo, a0hi);
        upk2(acc[i][1], a1lo, a1hi);
        size_t o0 = obase + (size_t)(2*i  )*5*4096;
        size_t o1 = obase + (size_t)(2*i+1)*5*4096;
        g_Y1[o0 + lane]      = fmaxf(a0lo, 0.f);
        g_Y1[o1 + lane]      = fmaxf(a0hi, 0.f);
        g_Y1[o0 + 32 + lane] = fmaxf(a1lo, 0.f);
        g_Y1[o1 + 32 + lane] = fmaxf(a1hi, 0.f);
    }
}

// ---------------- conv2: [64oc] x [64c x 7kd] over D(=5), + ReLU (w-pair packed) ----------------
#define C2_WS_OFF 20480                       // Ys[64][5][64]
#define C2_SMEM_FLOATS (C2_WS_OFF + 448*65)
#define C2_SMEM_BYTES  (C2_SMEM_FLOATS*4)

__global__ __launch_bounds__(512)
void conv2_kernel(const float* __restrict__ W2, float* __restrict__ out)
{
    extern __shared__ float sm[];
    float* Ys = sm;               // [(c*5+d)*64 + w]
    float* Ws = sm + C2_WS_OFF;   // [(c*7+kd)*65 + oc]
    const int h = blockIdx.x, b = blockIdx.y;
    const int t = threadIdx.x;
    const int oc = t >> 3, wg = t & 7;

    for (int f = t; f < 5120; f += 512) {
        int r = f >> 4, w4 = f & 15;
        int c = r / 5, d = r % 5;
        *(float4*)(Ys + r*64 + w4*4) =
            *(const float4*)(g_Y1 + (((size_t)b*64 + c)*5 + d)*4096 + h*64 + w4*4);
    }
    for (int idx = t; idx < 64*448; idx += 512) {
        int o = idx / 448, r = idx % 448;
        Ws[r*65 + o] = W2[idx];
    }
    __syncthreads();

    ULL acc[5][4];
    #pragma unroll
    for (int d = 0; d < 5; d++)
        #pragma unroll
        for (int j = 0; j < 4; j++) acc[d][j] = 0ull;

    for (int c = 0; c < 64; c++) {
        ULL w2[7];
        #pragma unroll
        for (int kd = 0; kd < 7; kd++) {
            float wv = Ws[(c*7+kd)*65 + oc];
            w2[kd] = pk2(wv, wv);
        }
        #pragma unroll
        for (int dp = 0; dp < 5; dp++) {
            const float* yp = Ys + (c*5+dp)*64 + wg*8;
            ULL y2[4];
            #pragma unroll
            for (int j = 0; j < 4; j++) y2[j] = *(const ULL*)(yp + 2*j);
            #pragma unroll
            for (int d = 0; d < 5; d++) {
                int kd = dp - d + 3;
                if (kd < 0 || kd > 6) continue;     // compile-time pruned
                #pragma unroll
                for (int j = 0; j < 4; j++) acc[d][j] = ffma2(w2[kd], y2[j], acc[d][j]);
            }
        }
    }
    #pragma unroll
    for (int d = 0; d < 5; d++) {
        size_t idx = (((size_t)b*64 + oc)*5 + d)*4096 + h*64 + wg*8;
        #pragma unroll
        for (int j = 0; j < 4; j++) {
            float lo, hi; upk2(acc[d][j], lo, hi);
            *(float2*)(out + idx + 2*j) = make_float2(fmaxf(lo, 0.f), fmaxf(hi, 0.f));
        }
    }
}

// ---------------- launch ----------------
extern "C" void kernel_launch(void* const* d_in, const int* in_sizes, int n_in,
                              void* d_out, int out_size)
{
    const float* buffer = (const float*)d_in[0];
    const float* Wq = (const float*)d_in[1];
    const float* Wk = (const float*)d_in[2];
    const float* Wv = (const float*)d_in[3];
    const float* Wc = (const float*)d_in[4];
    const float* W1 = (const float*)d_in[5];
    const float* W2 = (const float*)d_in[6];
    float* out = (float*)d_out;

    cudaFuncSetAttribute(attn_kernel,  cudaFuncAttributeMaxDynamicSharedMemorySize, ATTN_SMEM_BYTES);
    cudaFuncSetAttribute(conv1_kernel, cudaFuncAttributeMaxDynamicSharedMemorySize, C1_SMEM_BYTES);
    cudaFuncSetAttribute(conv2_kernel, cudaFuncAttributeMaxDynamicSharedMemorySize, C2_SMEM_BYTES);

    attn_kernel <<<dim3(64, 8),    512, ATTN_SMEM_BYTES>>>(buffer, Wq, Wk, Wv, Wc);
    conv1_kernel<<<dim3(64, 5, 8), 256, C1_SMEM_BYTES>>>(W1);
    conv2_kernel<<<dim3(64, 8),    512, C2_SMEM_BYTES>>>(W2, out);
}

// round 6
// speedup vs baseline: 1.2186x; 1.1626x over previous
#include <cuda_runtime.h>

typedef unsigned long long ULL;

// ---------------- f32x2 helpers ----------------
__device__ __forceinline__ ULL pk2(float lo, float hi) {
    ULL r; asm("mov.b64 %0, {%1, %2};" : "=l"(r) : "f"(lo), "f"(hi)); return r;
}
__device__ __forceinline__ void upk2(ULL v, float& lo, float& hi) {
    asm("mov.b64 {%0, %1}, %2;" : "=f"(lo), "=f"(hi) : "l"(v));
}
__device__ __forceinline__ ULL ffma2(ULL a, ULL b, ULL c) {
    ULL d; asm("fma.rn.f32x2 %0, %1, %2, %3;" : "=l"(d) : "l"(a), "l"(b), "l"(c));
    return d;
}
__device__ __forceinline__ int remap(int n) { return (n / 40) * 42 + (n % 40); }

// ---------------- scratch ----------------
__device__ float g_X [8*40*5*64*64];   // [b][c8*5+v][ar][h][w]
__device__ float g_Y1[8*64*5*64*64];   // [b][c][ar][h][w]

// ---------------- attn smem layout (floats) ----------------
#define PSS 336                  // P row stride: 8 chunks * 42 (footprint 334)
#define VSS 344                  // V row stride: >=334, and 344%32==24 -> bank bijection
#define SM_PS   0                // Ps[64][336]=21504 ; Bs[64][320]=20480 overlays
#define SM_Q    21504            // Q[8][320] plain
#define SM_K    24064            // K[8][320] plain
#define SM_V    26624            // V[40][344] chunked = 13760
#define SM_WD   40384            // dup weights [c][96][2] = 12288
#define SM_RINV 52672            // [64]
#define ATTN_SMEM_FLOATS 52736
#define ATTN_SMEM_BYTES  (ATTN_SMEM_FLOATS*4)

__global__ __launch_bounds__(512)
void attn_kernel(const float* __restrict__ buffer,
                 const float* __restrict__ Wq, const float* __restrict__ Wk,
                 const float* __restrict__ Wv, const float* __restrict__ Wc)
{
    extern __shared__ float sm[];
    float* Bs   = sm;            // Phase A input, overlaid by Ps afterwards
    float* rinv = sm + SM_RINV;

    const int h    = blockIdx.x;
    const int b    = blockIdx.y;
    const int t    = threadIdx.x;
    const int lane = t & 31;
    const int wid  = t >> 5;     // 16 warps

    // ---- weights -> smem, duplicated into f32x2 pairs ----
    for (int idx = t; idx < 96*64; idx += 512) {
        int oc = idx >> 6, c = idx & 63;
        float v;
        if      (oc <  8) v = Wq[(oc      )*64 + c];
        else if (oc < 16) v = Wk[(oc -  8)*64 + c];
        else if (oc < 56) v = Wv[(oc - 16)*64 + c];
        else              v = Wc[(oc - 56)*64 + c];
        sm[SM_WD + c*192 + oc*2    ] = v;
        sm[SM_WD + c*192 + oc*2 + 1] = v;
    }
    // ---- buffer slice Bs[c][v*64+w] ----
    for (int f = t; f < 5120; f += 512) {
        int r  = f >> 4;
        int w4 = f & 15;
        int c = r / 5, v = r % 5;
        float4 val = *(const float4*)(buffer + (((size_t)(b*64 + c)*5 + v)*4096 + h*64 + w4*4));
        *(float4*)(Bs + c*320 + v*64 + w4*4) = val;
    }
    __syncthreads();

    // ---- Phase A: [96oc x 64c] x [64c x 320n], n-pair packed ----
    {
        const int ocb = wid * 6;
        ULL acc[6][5];
        #pragma unroll
        for (int i = 0; i < 6; i++)
            #pragma unroll
            for (int jp = 0; jp < 5; jp++) acc[i][jp] = 0ull;

        for (int c = 0; c < 64; c++) {
            ULL w2[6];
            #pragma unroll
            for (int i = 0; i < 6; i++)
                w2[i] = *(const ULL*)(sm + SM_WD + c*192 + (ocb + i)*2);
            #pragma unroll
            for (int jp = 0; jp < 5; jp++) {
                ULL b2 = *(const ULL*)(Bs + c*320 + 2*lane + 64*jp);
                #pragma unroll
                for (int i = 0; i < 6; i++) acc[i][jp] = ffma2(w2[i], b2, acc[i][jp]);
            }
        }
        #pragma unroll
        for (int i = 0; i < 6; i++) {
            int oc = ocb + i;
            #pragma unroll
            for (int jp = 0; jp < 5; jp++) {
                int n = 2*lane + 64*jp;
                if (oc < 8)       *(ULL*)(sm + SM_Q + oc*320 + n)              = acc[i][jp];
                else if (oc < 16) *(ULL*)(sm + SM_K + (oc-8)*320 + n)          = acc[i][jp];
                else if (oc < 56) *(ULL*)(sm + SM_V + (oc-16)*VSS + remap(n))  = acc[i][jp];
                else {
                    int cc = oc - 56;          // c8*5 + ar
                    int c8 = cc / 5, ar = cc % 5;
                    float lo, hi; upk2(acc[i][jp], lo, hi);
                    size_t idx = ((((size_t)b*40 + c8*5 + jp)*5 + ar)*64 + h)*64 + 2*lane;
                    *(float2*)(g_X + idx) = make_float2(lo, hi);
                }
            }
        }
    }
    __syncthreads();

    // ---- Phase B: 5 tiles of 64 rows ----
    for (int tile = 0; tile < 5; tile++) {
        const int m0 = tile * 64;

        // B1: scores (scalar, inner dim 8) + softmax -> Ps (chunked), rinv
        {
            float q[4][8];
            #pragma unroll
            for (int mi = 0; mi < 4; mi++)
                #pragma unroll
                for (int d = 0; d < 8; d++)
                    q[mi][d] = sm[SM_Q + d*320 + m0 + wid*4 + mi];

            float s[4][10];
            #pragma unroll
            for (int j = 0; j < 10; j++) {
                int n = lane + 32*j;
                float kv[8];
                #pragma unroll
                for (int d = 0; d < 8; d++) kv[d] = sm[SM_K + d*320 + n];
                #pragma unroll
                for (int mi = 0; mi < 4; mi++) {
                    float a = 0.f;
                    #pragma unroll
                    for (int d = 0; d < 8; d++) a += q[mi][d]*kv[d];
                    s[mi][j] = a;
                }
            }
            #pragma unroll
            for (int mi = 0; mi < 4; mi++) {
                float mx = s[mi][0];
                #pragma unroll
                for (int j = 1; j < 10; j++) mx = fmaxf(mx, s[mi][j]);
                #pragma unroll
                for (int o = 16; o; o >>= 1) mx = fmaxf(mx, __shfl_xor_sync(0xffffffffu, mx, o));
                float sum = 0.f;
                int r = wid*4 + mi;
                #pragma unroll
                for (int j = 0; j < 10; j++) {
                    float e = __expf(s[mi][j] - mx);
                    sum += e;
                    sm[SM_PS + r*PSS + remap(lane + 32*j)] = e;
                }
                #pragma unroll
                for (int o = 16; o; o >>= 1) sum += __shfl_xor_sync(0xffffffffu, sum, o);
                if (lane == 0) rinv[r] = 1.0f / sum;
            }
        }
        __syncthreads();

        // B2: O[64][40] = P[64][320] * V^T  (4 rows x 5 ocs per thread, n-split 4)
        {
            const int ocgrp = lane >> 2;     // 0..7
            const int l4    = lane & 3;      // n-split lane

            ULL acc[4][5];
            #pragma unroll
            for (int ri = 0; ri < 4; ri++)
                #pragma unroll
                for (int i = 0; i < 5; i++) acc[ri][i] = 0ull;

            const float* pbase = sm + SM_PS + (wid*4)*PSS;
            const float* vbase = sm + SM_V  + (ocgrp*5)*VSS;

            #pragma unroll
            for (int phase = 0; phase < 2; phase++) {
                const int co = (l4 + 4*phase) * 42;     // chunk offset
                for (int j = 0; j < 20; j++) {
                    ULL p2[4];
                    #pragma unroll
                    for (int ri = 0; ri < 4; ri++)
                        p2[ri] = *(const ULL*)(pbase + ri*PSS + co + 2*j);
                    #pragma unroll
                    for (int i = 0; i < 5; i++) {
                        ULL v2 = *(const ULL*)(vbase + i*VSS + co + 2*j);
                        #pragma unroll
                        for (int ri = 0; ri < 4; ri++)
                            acc[ri][i] = ffma2(p2[ri], v2, acc[ri][i]);
                    }
                }
            }

            // reduce over 4 n-split lanes (xor 1,2 within l4 group)
            float red[4][5];
            #pragma unroll
            for (int ri = 0; ri < 4; ri++)
                #pragma unroll
                for (int i = 0; i < 5; i++) {
                    float lo, hi; upk2(acc[ri][i], lo, hi);
                    float a = lo + hi;
                    a += __shfl_xor_sync(0xffffffffu, a, 1);
                    a += __shfl_xor_sync(0xffffffffu, a, 2);
                    red[ri][i] = a;
                }
            #pragma unroll
            for (int ri = 0; ri < 4; ri++) {
                if (l4 == ri) {
                    int r = wid*4 + ri;        // tile-local row; v = tile, w = r
                    float scale = rinv[r];
                    #pragma unroll
                    for (int i = 0; i < 5; i++) {
                        size_t idx = ((((size_t)b*40 + ocgrp*5 + tile)*5 + i)*64 + h)*64 + r;
                        g_X[idx] += scale * red[ri][i];
                    }
                }
            }
        }
        __syncthreads();
    }
}

// ---------------- conv1: [64oc] x [40ci x 7kw] over W, + ReLU (oc-pair packed) ----------------
#define C1_WS_OFF 2880                       // Xs[40][72]
#define C1_SMEM_FLOATS (C1_WS_OFF + 280*66)
#define C1_SMEM_BYTES  (C1_SMEM_FLOATS*4)

__global__ __launch_bounds__(256)
void conv1_kernel(const float* __restrict__ W1)
{
    extern __shared__ float sm[];
    float* Xs = sm;               // [ci][72], data at [ci][3+w]
    float* Ws = sm + C1_WS_OFF;   // [(ci*7+kw)*66 + oc]
    const int h = blockIdx.x, d = blockIdx.y, b = blockIdx.z;
    const int t = threadIdx.x, lane = t & 31;
    const int ocb = (t >> 5) * 8;

    for (int idx = t; idx < 240; idx += 256) {
        int ci = idx / 6, p = idx % 6;
        Xs[ci*72 + (p < 3 ? p : 64 + p)] = 0.f;
    }
    for (int idx = t; idx < 40*64; idx += 256) {
        int ci = idx >> 6, w = idx & 63;
        Xs[ci*72 + 3 + w] = g_X[(((size_t)b*40 + ci)*5 + d)*4096 + h*64 + w];
    }
    for (int idx = t; idx < 64*280; idx += 256) {
        int oc = idx / 280, r = idx % 280;
        Ws[r*66 + oc] = W1[idx];
    }
    __syncthreads();

    ULL acc[4][2];
    #pragma unroll
    for (int i = 0; i < 4; i++) { acc[i][0] = 0ull; acc[i][1] = 0ull; }

    for (int ci = 0; ci < 40; ci++) {
        #pragma unroll
        for (int kw = 0; kw < 7; kw++) {
            float x0 = Xs[ci*72 + lane + kw];
            float x1 = Xs[ci*72 + 32 + lane + kw];
            ULL xx0 = pk2(x0, x0), xx1 = pk2(x1, x1);
            const float* wp = Ws + (ci*7+kw)*66 + ocb;
            #pragma unroll
            for (int i = 0; i < 4; i++) {
                ULL w2 = *(const ULL*)(wp + 2*i);
                acc[i][0] = ffma2(w2, xx0, acc[i][0]);
                acc[i][1] = ffma2(w2, xx1, acc[i][1]);
            }
        }
    }
    size_t obase = (((size_t)b*64 + ocb)*5 + d)*4096 + h*64;
    #pragma unroll
    for (int i = 0; i < 4; i++) {
        float a0lo, a0hi, a1lo, a1hi;
        upk2(acc[i][0], a0lo, a0hi);
        upk2(acc[i][1], a1lo, a1hi);
        size_t o0 = obase + (size_t)(2*i  )*5*4096;
        size_t o1 = obase + (size_t)(2*i+1)*5*4096;
        g_Y1[o0 + lane]      = fmaxf(a0lo, 0.f);
        g_Y1[o1 + lane]      = fmaxf(a0hi, 0.f);
        g_Y1[o0 + 32 + lane] = fmaxf(a1lo, 0.f);
        g_Y1[o1 + 32 + lane] = fmaxf(a1hi, 0.f);
    }
}

// ---------------- conv2: [64oc] x [64c x 7kd] over D(=5), + ReLU (w-pair packed) ----------------
#define C2_WS_OFF 20480                       // Ys[64][5][64]
#define C2_SMEM_FLOATS (C2_WS_OFF + 448*65)
#define C2_SMEM_BYTES  (C2_SMEM_FLOATS*4)

__global__ __launch_bounds__(512)
void conv2_kernel(const float* __restrict__ W2, float* __restrict__ out)
{
    extern __shared__ float sm[];
    float* Ys = sm;               // [(c*5+d)*64 + w]
    float* Ws = sm + C2_WS_OFF;   // [(c*7+kd)*65 + oc]
    const int h = blockIdx.x, b = blockIdx.y;
    const int t = threadIdx.x;
    const int oc = t >> 3, wg = t & 7;

    for (int f = t; f < 5120; f += 512) {
        int r = f >> 4, w4 = f & 15;
        int c = r / 5, d = r % 5;
        *(float4*)(Ys + r*64 + w4*4) =
            *(const float4*)(g_Y1 + (((size_t)b*64 + c)*5 + d)*4096 + h*64 + w4*4);
    }
    for (int idx = t; idx < 64*448; idx += 512) {
        int o = idx / 448, r = idx % 448;
        Ws[r*65 + o] = W2[idx];
    }
    __syncthreads();

    ULL acc[5][4];
    #pragma unroll
    for (int d = 0; d < 5; d++)
        #pragma unroll
        for (int j = 0; j < 4; j++) acc[d][j] = 0ull;

    for (int c = 0; c < 64; c++) {
        ULL w2[7];
        #pragma unroll
        for (int kd = 0; kd < 7; kd++) {
            float wv = Ws[(c*7+kd)*65 + oc];
            w2[kd] = pk2(wv, wv);
        }
        #pragma unroll
        for (int dp = 0; dp < 5; dp++) {
            const float* yp = Ys + (c*5+dp)*64 + wg*8;
            ULL y2[4];
            #pragma unroll
            for (int j = 0; j < 4; j++) y2[j] = *(const ULL*)(yp + 2*j);
            #pragma unroll
            for (int d = 0; d < 5; d++) {
                int kd = dp - d + 3;
                if (kd < 0 || kd > 6) continue;     // compile-time pruned
                #pragma unroll
                for (int j = 0; j < 4; j++) acc[d][j] = ffma2(w2[kd], y2[j], acc[d][j]);
            }
        }
    }
    #pragma unroll
    for (int d = 0; d < 5; d++) {
        size_t idx = (((size_t)b*64 + oc)*5 + d)*4096 + h*64 + wg*8;
        #pragma unroll
        for (int j = 0; j < 4; j++) {
            float lo, hi; upk2(acc[d][j], lo, hi);
            *(float2*)(out + idx + 2*j) = make_float2(fmaxf(lo, 0.f), fmaxf(hi, 0.f));
        }
    }
}

// ---------------- launch ----------------
extern "C" void kernel_launch(void* const* d_in, const int* in_sizes, int n_in,
                              void* d_out, int out_size)
{
    const float* buffer = (const float*)d_in[0];
    const float* Wq = (const float*)d_in[1];
    const float* Wk = (const float*)d_in[2];
    const float* Wv = (const float*)d_in[3];
    const float* Wc = (const float*)d_in[4];
    const float* W1 = (const float*)d_in[5];
    const float* W2 = (const float*)d_in[6];
    float* out = (float*)d_out;

    cudaFuncSetAttribute(attn_kernel,  cudaFuncAttributeMaxDynamicSharedMemorySize, ATTN_SMEM_BYTES);
    cudaFuncSetAttribute(conv1_kernel, cudaFuncAttributeMaxDynamicSharedMemorySize, C1_SMEM_BYTES);
    cudaFuncSetAttribute(conv2_kernel, cudaFuncAttributeMaxDynamicSharedMemorySize, C2_SMEM_BYTES);

    attn_kernel <<<dim3(64, 8),    512, ATTN_SMEM_BYTES>>>(buffer, Wq, Wk, Wv, Wc);
    conv1_kernel<<<dim3(64, 5, 8), 256, C1_SMEM_BYTES>>>(W1);
    conv2_kernel<<<dim3(64, 8),    512, C2_SMEM_BYTES>>>(W2, out);
}

// round 7
// speedup vs baseline: 1.3669x; 1.1217x over previous
#include <cuda_runtime.h>

typedef unsigned long long ULL;

// ---------------- f32x2 helpers ----------------
__device__ __forceinline__ ULL pk2(float lo, float hi) {
    ULL r; asm("mov.b64 %0, {%1, %2};" : "=l"(r) : "f"(lo), "f"(hi)); return r;
}
__device__ __forceinline__ void upk2(ULL v, float& lo, float& hi) {
    asm("mov.b64 {%0, %1}, %2;" : "=f"(lo), "=f"(hi) : "l"(v));
}
__device__ __forceinline__ ULL ffma2(ULL a, ULL b, ULL c) {
    ULL d; asm("fma.rn.f32x2 %0, %1, %2, %3;" : "=l"(d) : "l"(a), "l"(b), "l"(c));
    return d;
}
__device__ __forceinline__ int remap(int n) { return (n / 40) * 42 + (n % 40); }

// ---------------- scratch ----------------
__device__ float g_X [8*40*5*64*64];   // [b][c8*5+v][ar][h][w]
__device__ float g_Y1[8*64*5*64*64];   // [b][c][ar][h][w]

// ---------------- attn smem layout (floats) ----------------
#define PSS 336                  // P row stride: 8 chunks * 42 (footprint 334)
#define VSS 344                  // V row stride: >=334, 344%32==24 -> bank bijection
#define SM_PS   0                // Ps[64][336]=21504 ; Bs[64][320]=20480 overlays
#define SM_Q    21504            // Q[8][320] plain
#define SM_K    24064            // K[8][320] plain
#define SM_V    26624            // V[40][344] chunked = 13760
#define SM_WD   40384            // dup weights [c][96][2] = 12288
#define SM_RINV 52672            // [64]
#define ATTN_SMEM_FLOATS 52736
#define ATTN_SMEM_BYTES  (ATTN_SMEM_FLOATS*4)

__global__ __launch_bounds__(1024)
void attn_kernel(const float* __restrict__ buffer,
                 const float* __restrict__ Wq, const float* __restrict__ Wk,
                 const float* __restrict__ Wv, const float* __restrict__ Wc)
{
    extern __shared__ float sm[];
    float* Bs   = sm;            // Phase A input, overlaid by Ps afterwards
    float* rinv = sm + SM_RINV;

    const int h    = blockIdx.x;
    const int b    = blockIdx.y;
    const int t    = threadIdx.x;
    const int lane = t & 31;
    const int wid  = t >> 5;     // 32 warps

    // ---- weights -> smem, duplicated into f32x2 pairs ----
    for (int idx = t; idx < 96*64; idx += 1024) {
        int oc = idx >> 6, c = idx & 63;
        float v;
        if      (oc <  8) v = Wq[(oc      )*64 + c];
        else if (oc < 16) v = Wk[(oc -  8)*64 + c];
        else if (oc < 56) v = Wv[(oc - 16)*64 + c];
        else              v = Wc[(oc - 56)*64 + c];
        sm[SM_WD + c*192 + oc*2    ] = v;
        sm[SM_WD + c*192 + oc*2 + 1] = v;
    }
    // ---- buffer slice Bs[c][v*64+w] ----
    for (int f = t; f < 5120; f += 1024) {
        int r  = f >> 4;
        int w4 = f & 15;
        int c = r / 5, v = r % 5;
        float4 val = *(const float4*)(buffer + (((size_t)(b*64 + c)*5 + v)*4096 + h*64 + w4*4));
        *(float4*)(Bs + c*320 + v*64 + w4*4) = val;
    }
    __syncthreads();

    // ---- Phase A: [96oc x 64c] x [64c x 320n], 3 oc per warp ----
    {
        const int ocb = wid * 3;
        ULL acc[3][5];
        #pragma unroll
        for (int i = 0; i < 3; i++)
            #pragma unroll
            for (int jp = 0; jp < 5; jp++) acc[i][jp] = 0ull;

        for (int c = 0; c < 64; c++) {
            ULL w2[3];
            #pragma unroll
            for (int i = 0; i < 3; i++)
                w2[i] = *(const ULL*)(sm + SM_WD + c*192 + (ocb + i)*2);
            #pragma unroll
            for (int jp = 0; jp < 5; jp++) {
                ULL b2 = *(const ULL*)(Bs + c*320 + 2*lane + 64*jp);
                #pragma unroll
                for (int i = 0; i < 3; i++) acc[i][jp] = ffma2(w2[i], b2, acc[i][jp]);
            }
        }
        #pragma unroll
        for (int i = 0; i < 3; i++) {
            int oc = ocb + i;
            #pragma unroll
            for (int jp = 0; jp < 5; jp++) {
                int n = 2*lane + 64*jp;
                if (oc < 8)       *(ULL*)(sm + SM_Q + oc*320 + n)              = acc[i][jp];
                else if (oc < 16) *(ULL*)(sm + SM_K + (oc-8)*320 + n)          = acc[i][jp];
                else if (oc < 56) *(ULL*)(sm + SM_V + (oc-16)*VSS + remap(n))  = acc[i][jp];
                else {
                    int cc = oc - 56;          // c8*5 + ar
                    int c8 = cc / 5, ar = cc % 5;
                    float lo, hi; upk2(acc[i][jp], lo, hi);
                    size_t idx = ((((size_t)b*40 + c8*5 + jp)*5 + ar)*64 + h)*64 + 2*lane;
                    *(float2*)(g_X + idx) = make_float2(lo, hi);
                }
            }
        }
    }
    __syncthreads();

    // ---- Phase B: 5 tiles of 64 rows ----
    for (int tile = 0; tile < 5; tile++) {
        const int m0 = tile * 64;

        // B1: scores (scalar, inner dim 8) + softmax -> Ps (chunked), rinv. 2 rows/warp.
        {
            float q[2][8];
            #pragma unroll
            for (int mi = 0; mi < 2; mi++)
                #pragma unroll
                for (int d = 0; d < 8; d++)
                    q[mi][d] = sm[SM_Q + d*320 + m0 + wid*2 + mi];

            float s[2][10];
            #pragma unroll
            for (int j = 0; j < 10; j++) {
                int n = lane + 32*j;
                float kv[8];
                #pragma unroll
                for (int d = 0; d < 8; d++) kv[d] = sm[SM_K + d*320 + n];
                #pragma unroll
                for (int mi = 0; mi < 2; mi++) {
                    float a = 0.f;
                    #pragma unroll
                    for (int d = 0; d < 8; d++) a += q[mi][d]*kv[d];
                    s[mi][j] = a;
                }
            }
            #pragma unroll
            for (int mi = 0; mi < 2; mi++) {
                float mx = s[mi][0];
                #pragma unroll
                for (int j = 1; j < 10; j++) mx = fmaxf(mx, s[mi][j]);
                #pragma unroll
                for (int o = 16; o; o >>= 1) mx = fmaxf(mx, __shfl_xor_sync(0xffffffffu, mx, o));
                float sum = 0.f;
                int r = wid*2 + mi;
                #pragma unroll
                for (int j = 0; j < 10; j++) {
                    float e = __expf(s[mi][j] - mx);
                    sum += e;
                    sm[SM_PS + r*PSS + remap(lane + 32*j)] = e;
                }
                #pragma unroll
                for (int o = 16; o; o >>= 1) sum += __shfl_xor_sync(0xffffffffu, sum, o);
                if (lane == 0) rinv[r] = 1.0f / sum;
            }
        }
        __syncthreads();

        // B2: O[64][40] = P[64][320] * V^T  (2 rows x 5 ocs per thread, n-split 4)
        {
            const int ocgrp = lane >> 2;     // 0..7
            const int l4    = lane & 3;      // n-split lane

            ULL acc[2][5];
            #pragma unroll
            for (int ri = 0; ri < 2; ri++)
                #pragma unroll
                for (int i = 0; i < 5; i++) acc[ri][i] = 0ull;

            const float* pbase = sm + SM_PS + (wid*2)*PSS;
            const float* vbase = sm + SM_V  + (ocgrp*5)*VSS;

            #pragma unroll
            for (int phase = 0; phase < 2; phase++) {
                const int co = (l4 + 4*phase) * 42;     // chunk offset
                for (int j = 0; j < 20; j++) {
                    ULL p2[2];
                    #pragma unroll
                    for (int ri = 0; ri < 2; ri++)
                        p2[ri] = *(const ULL*)(pbase + ri*PSS + co + 2*j);
                    #pragma unroll
                    for (int i = 0; i < 5; i++) {
                        ULL v2 = *(const ULL*)(vbase + i*VSS + co + 2*j);
                        #pragma unroll
                        for (int ri = 0; ri < 2; ri++)
                            acc[ri][i] = ffma2(p2[ri], v2, acc[ri][i]);
                    }
                }
            }

            // reduce over 4 n-split lanes
            float red[2][5];
            #pragma unroll
            for (int ri = 0; ri < 2; ri++)
                #pragma unroll
                for (int i = 0; i < 5; i++) {
                    float lo, hi; upk2(acc[ri][i], lo, hi);
                    float a = lo + hi;
                    a += __shfl_xor_sync(0xffffffffu, a, 1);
                    a += __shfl_xor_sync(0xffffffffu, a, 2);
                    red[ri][i] = a;
                }
            #pragma unroll
            for (int ri = 0; ri < 2; ri++) {
                if (l4 == ri) {
                    int r = wid*2 + ri;        // tile-local row; v = tile, w = r
                    float scale = rinv[r];
                    #pragma unroll
                    for (int i = 0; i < 5; i++) {
                        size_t idx = ((((size_t)b*40 + ocgrp*5 + tile)*5 + i)*64 + h)*64 + r;
                        g_X[idx] += scale * red[ri][i];
                    }
                }
            }
        }
        __syncthreads();
    }
}

// ---------------- conv1: 2 h-columns per CTA, [64oc] x [40ci x 7kw], + ReLU ----------------
#define C1X 2880                              // Xs per h: [40][72]
#define C1_WS_OFF (2*C1X)                     // 5760
#define C1_SMEM_FLOATS (C1_WS_OFF + 280*66)   // 24240
#define C1_SMEM_BYTES  (C1_SMEM_FLOATS*4)

__global__ __launch_bounds__(512)
void conv1_kernel(const float* __restrict__ W1)
{
    extern __shared__ float sm[];
    float* Ws = sm + C1_WS_OFF;   // [(ci*7+kw)*66 + oc]
    const int d = blockIdx.y, b = blockIdx.z;
    const int t = threadIdx.x;
    const int hh   = t >> 8;          // which h within pair
    const int tl   = t & 255;
    const int lane = tl & 31;
    const int ocb  = (tl >> 5) * 8;
    const int h    = blockIdx.x*2 + hh;

    // zero pads for both halves
    for (int idx = t; idx < 480; idx += 512) {
        int g = idx / 240, k = idx % 240;
        int ci = k / 6, p = k % 6;
        sm[g*C1X + ci*72 + (p < 3 ? p : 64 + p)] = 0.f;
    }
    // fill X rows for both h
    for (int idx = t; idx < 5120; idx += 512) {
        int g = idx / 2560, k = idx % 2560;
        int ci = k >> 6, w = k & 63;
        int hg = blockIdx.x*2 + g;
        sm[g*C1X + ci*72 + 3 + w] = g_X[(((size_t)b*40 + ci)*5 + d)*4096 + hg*64 + w];
    }
    // weights (shared by both halves)
    for (int idx = t; idx < 64*280; idx += 512) {
        int oc = idx / 280, r = idx % 280;
        Ws[r*66 + oc] = W1[idx];
    }
    __syncthreads();

    float* Xs = sm + hh*C1X;
    ULL acc[4][2];
    #pragma unroll
    for (int i = 0; i < 4; i++) { acc[i][0] = 0ull; acc[i][1] = 0ull; }

    for (int ci = 0; ci < 40; ci++) {
        #pragma unroll
        for (int kw = 0; kw < 7; kw++) {
            float x0 = Xs[ci*72 + lane + kw];
            float x1 = Xs[ci*72 + 32 + lane + kw];
            ULL xx0 = pk2(x0, x0), xx1 = pk2(x1, x1);
            const float* wp = Ws + (ci*7+kw)*66 + ocb;
            #pragma unroll
            for (int i = 0; i < 4; i++) {
                ULL w2 = *(const ULL*)(wp + 2*i);
                acc[i][0] = ffma2(w2, xx0, acc[i][0]);
                acc[i][1] = ffma2(w2, xx1, acc[i][1]);
            }
        }
    }
    size_t obase = (((size_t)b*64 + ocb)*5 + d)*4096 + h*64;
    #pragma unroll
    for (int i = 0; i < 4; i++) {
        float a0lo, a0hi, a1lo, a1hi;
        upk2(acc[i][0], a0lo, a0hi);
        upk2(acc[i][1], a1lo, a1hi);
        size_t o0 = obase + (size_t)(2*i  )*5*4096;
        size_t o1 = obase + (size_t)(2*i+1)*5*4096;
        g_Y1[o0 + lane]      = fmaxf(a0lo, 0.f);
        g_Y1[o1 + lane]      = fmaxf(a0hi, 0.f);
        g_Y1[o0 + 32 + lane] = fmaxf(a1lo, 0.f);
        g_Y1[o1 + 32 + lane] = fmaxf(a1hi, 0.f);
    }
}

// ---------------- conv2: [64oc] x [64c x 7kd] over D(=5), + ReLU, 1024 threads ----------------
#define C2_WS_OFF 20480                       // Ys[64][5][64]
#define C2_SMEM_FLOATS (C2_WS_OFF + 448*65)
#define C2_SMEM_BYTES  (C2_SMEM_FLOATS*4)

__global__ __launch_bounds__(1024)
void conv2_kernel(const float* __restrict__ W2, float* __restrict__ out)
{
    extern __shared__ float sm[];
    float* Ys = sm;               // [(c*5+d)*64 + w]
    float* Ws = sm + C2_WS_OFF;   // [(c*7+kd)*65 + oc]
    const int h = blockIdx.x, b = blockIdx.y;
    const int t = threadIdx.x;
    const int oc = t >> 4, wg = t & 15;     // 4 w per thread

    for (int f = t; f < 5120; f += 1024) {
        int r = f >> 4, w4 = f & 15;
        int c = r / 5, d = r % 5;
        *(float4*)(Ys + r*64 + w4*4) =
            *(const float4*)(g_Y1 + (((size_t)b*64 + c)*5 + d)*4096 + h*64 + w4*4);
    }
    for (int idx = t; idx < 64*448; idx += 1024) {
        int o = idx / 448, r = idx % 448;
        Ws[r*65 + o] = W2[idx];
    }
    __syncthreads();

    ULL acc[5][2];
    #pragma unroll
    for (int d = 0; d < 5; d++) { acc[d][0] = 0ull; acc[d][1] = 0ull; }

    for (int c = 0; c < 64; c++) {
        ULL w2[7];
        #pragma unroll
        for (int kd = 0; kd < 7; kd++) {
            float wv = Ws[(c*7+kd)*65 + oc];
            w2[kd] = pk2(wv, wv);
        }
        #pragma unroll
        for (int dp = 0; dp < 5; dp++) {
            const float* yp = Ys + (c*5+dp)*64 + wg*4;
            ULL y20 = *(const ULL*)yp;
            ULL y21 = *(const ULL*)(yp + 2);
            #pragma unroll
            for (int d = 0; d < 5; d++) {
                int kd = dp - d + 3;
                if (kd < 0 || kd > 6) continue;     // compile-time pruned
                acc[d][0] = ffma2(w2[kd], y20, acc[d][0]);
                acc[d][1] = ffma2(w2[kd], y21, acc[d][1]);
            }
        }
    }
    #pragma unroll
    for (int d = 0; d < 5; d++) {
        size_t idx = (((size_t)b*64 + oc)*5 + d)*4096 + h*64 + wg*4;
        float lo0, hi0, lo1, hi1;
        upk2(acc[d][0], lo0, hi0);
        upk2(acc[d][1], lo1, hi1);
        *(float2*)(out + idx)     = make_float2(fmaxf(lo0, 0.f), fmaxf(hi0, 0.f));
        *(float2*)(out + idx + 2) = make_float2(fmaxf(lo1, 0.f), fmaxf(hi1, 0.f));
    }
}

// ---------------- launch ----------------
extern "C" void kernel_launch(void* const* d_in, const int* in_sizes, int n_in,
                              void* d_out, int out_size)
{
    const float* buffer = (const float*)d_in[0];
    const float* Wq = (const float*)d_in[1];
    const float* Wk = (const float*)d_in[2];
    const float* Wv = (const float*)d_in[3];
    const float* Wc = (const float*)d_in[4];
    const float* W1 = (const float*)d_in[5];
    const float* W2 = (const float*)d_in[6];
    float* out = (float*)d_out;

    cudaFuncSetAttribute(attn_kernel,  cudaFuncAttributeMaxDynamicSharedMemorySize, ATTN_SMEM_BYTES);
    cudaFuncSetAttribute(conv1_kernel, cudaFuncAttributeMaxDynamicSharedMemorySize, C1_SMEM_BYTES);
    cudaFuncSetAttribute(conv2_kernel, cudaFuncAttributeMaxDynamicSharedMemorySize, C2_SMEM_BYTES);

    attn_kernel <<<dim3(64, 8),    1024, ATTN_SMEM_BYTES>>>(buffer, Wq, Wk, Wv, Wc);
    conv1_kernel<<<dim3(32, 5, 8),  512, C1_SMEM_BYTES>>>(W1);
    conv2_kernel<<<dim3(64, 8),    1024, C2_SMEM_BYTES>>>(W2, out);
}

// round 8
// speedup vs baseline: 1.6042x; 1.1736x over previous
#include <cuda_runtime.h>

typedef unsigned long long ULL;

// ---------------- f32x2 helpers ----------------
__device__ __forceinline__ ULL pk2(float lo, float hi) {
    ULL r; asm("mov.b64 %0, {%1, %2};" : "=l"(r) : "f"(lo), "f"(hi)); return r;
}
__device__ __forceinline__ void upk2(ULL v, float& lo, float& hi) {
    asm("mov.b64 {%0, %1}, %2;" : "=f"(lo), "=f"(hi) : "l"(v));
}
__device__ __forceinline__ ULL ffma2(ULL a, ULL b, ULL c) {
    ULL d; asm("fma.rn.f32x2 %0, %1, %2, %3;" : "=l"(d) : "l"(a), "l"(b), "l"(c));
    return d;
}
__device__ __forceinline__ int remap(int n) { return (n / 40) * 42 + (n % 40); }

// ---------------- scratch ----------------
__device__ float g_X [8*40*5*64*64];   // [b][c8*5+v][ar][h][w]
__device__ float g_Y1[8*64*5*64*64];   // [b][c][ar][h][w]

// ---------------- attn smem layout (floats) ----------------
#define PSS 338                  // P row stride: >=334, 2*PSS%16==4 -> rowsub/l4 bank bijection
#define VSS 340                  // V row stride: >=334, (5*VSS/2)%4==2 -> ocsub/l4 conflict-free
#define SM_PS   0                // Ps[64][338]=21632 ; Bs[64][320]=20480 overlays
#define SM_Q    21632            // Q[8][320] plain
#define SM_K    24192            // K[8][320] plain
#define SM_V    26752            // V[40][340] chunked = 13600
#define SM_WD   40352            // dup weights [c][96][2] = 12288
#define SM_RINV 52640            // [64]
#define ATTN_SMEM_FLOATS 52704
#define ATTN_SMEM_BYTES  (ATTN_SMEM_FLOATS*4)

__global__ __launch_bounds__(512)
void attn_kernel(const float* __restrict__ buffer,
                 const float* __restrict__ Wq, const float* __restrict__ Wk,
                 const float* __restrict__ Wv, const float* __restrict__ Wc)
{
    extern __shared__ float sm[];
    float* Bs   = sm;            // Phase A input, overlaid by Ps afterwards
    float* rinv = sm + SM_RINV;

    const int h    = blockIdx.x;
    const int b    = blockIdx.y;
    const int t    = threadIdx.x;
    const int lane = t & 31;
    const int wid  = t >> 5;     // 16 warps

    // ---- weights -> smem, duplicated into f32x2 pairs ----
    for (int idx = t; idx < 96*64; idx += 512) {
        int oc = idx >> 6, c = idx & 63;
        float v;
        if      (oc <  8) v = Wq[(oc      )*64 + c];
        else if (oc < 16) v = Wk[(oc -  8)*64 + c];
        else if (oc < 56) v = Wv[(oc - 16)*64 + c];
        else              v = Wc[(oc - 56)*64 + c];
        sm[SM_WD + c*192 + oc*2    ] = v;
        sm[SM_WD + c*192 + oc*2 + 1] = v;
    }
    // ---- buffer slice Bs[c][v*64+w] ----
    for (int f = t; f < 5120; f += 512) {
        int r  = f >> 4;
        int w4 = f & 15;
        int c = r / 5, v = r % 5;
        float4 val = *(const float4*)(buffer + (((size_t)(b*64 + c)*5 + v)*4096 + h*64 + w4*4));
        *(float4*)(Bs + c*320 + v*64 + w4*4) = val;
    }
    __syncthreads();

    // ---- Phase A: [96oc x 64c] x [64c x 320n], 6 oc per warp ----
    {
        const int ocb = wid * 6;
        ULL acc[6][5];
        #pragma unroll
        for (int i = 0; i < 6; i++)
            #pragma unroll
            for (int jp = 0; jp < 5; jp++) acc[i][jp] = 0ull;

        for (int c = 0; c < 64; c++) {
            ULL w2[6];
            #pragma unroll
            for (int i = 0; i < 6; i++)
                w2[i] = *(const ULL*)(sm + SM_WD + c*192 + (ocb + i)*2);
            #pragma unroll
            for (int jp = 0; jp < 5; jp++) {
                ULL b2 = *(const ULL*)(Bs + c*320 + 2*lane + 64*jp);
                #pragma unroll
                for (int i = 0; i < 6; i++) acc[i][jp] = ffma2(w2[i], b2, acc[i][jp]);
            }
        }
        #pragma unroll
        for (int i = 0; i < 6; i++) {
            int oc = ocb + i;
            #pragma unroll
            for (int jp = 0; jp < 5; jp++) {
                int n = 2*lane + 64*jp;
                if (oc < 8)       *(ULL*)(sm + SM_Q + oc*320 + n)              = acc[i][jp];
                else if (oc < 16) *(ULL*)(sm + SM_K + (oc-8)*320 + n)          = acc[i][jp];
                else if (oc < 56) *(ULL*)(sm + SM_V + (oc-16)*VSS + remap(n))  = acc[i][jp];
                else {
                    int cc = oc - 56;          // c8*5 + ar
                    int c8 = cc / 5, ar = cc % 5;
                    float lo, hi; upk2(acc[i][jp], lo, hi);
                    size_t idx = ((((size_t)b*40 + c8*5 + jp)*5 + ar)*64 + h)*64 + 2*lane;
                    *(float2*)(g_X + idx) = make_float2(lo, hi);
                }
            }
        }
    }
    __syncthreads();

    // ---- Phase B: 5 tiles of 64 rows ----
    for (int tile = 0; tile < 5; tile++) {
        const int m0 = tile * 64;

        // B1: scores (scalar, inner dim 8) + softmax -> Ps (chunked), rinv. 4 rows/warp.
        {
            float q[4][8];
            #pragma unroll
            for (int mi = 0; mi < 4; mi++)
                #pragma unroll
                for (int d = 0; d < 8; d++)
                    q[mi][d] = sm[SM_Q + d*320 + m0 + wid*4 + mi];

            float s[4][10];
            #pragma unroll
            for (int j = 0; j < 10; j++) {
                int n = lane + 32*j;
                float kv[8];
                #pragma unroll
                for (int d = 0; d < 8; d++) kv[d] = sm[SM_K + d*320 + n];
                #pragma unroll
                for (int mi = 0; mi < 4; mi++) {
                    float a = 0.f;
                    #pragma unroll
                    for (int d = 0; d < 8; d++) a += q[mi][d]*kv[d];
                    s[mi][j] = a;
                }
            }
            #pragma unroll
            for (int mi = 0; mi < 4; mi++) {
                float mx = s[mi][0];
                #pragma unroll
                for (int j = 1; j < 10; j++) mx = fmaxf(mx, s[mi][j]);
                #pragma unroll
                for (int o = 16; o; o >>= 1) mx = fmaxf(mx, __shfl_xor_sync(0xffffffffu, mx, o));
                float sum = 0.f;
                int r = wid*4 + mi;
                #pragma unroll
                for (int j = 0; j < 10; j++) {
                    float e = __expf(s[mi][j] - mx);
                    sum += e;
                    sm[SM_PS + r*PSS + remap(lane + 32*j)] = e;
                }
                #pragma unroll
                for (int o = 16; o; o >>= 1) sum += __shfl_xor_sync(0xffffffffu, sum, o);
                if (lane == 0) rinv[r] = 1.0f / sum;
            }
        }
        __syncthreads();

        // B2: O[64][40] = P[64][320] * V^T
        // warp tile: 16 rows x 10 ocs; thread: 4 rows x 5 ocs, n-split 4
        {
            const int l4     = lane & 3;        // n-split
            const int ocsub  = (lane >> 2) & 1; // 2 oc sub-blocks of 5
            const int rowsub = lane >> 3;       // 4 row sub-blocks of 4
            const int oc_b   = wid & 3;         // 4 oc blocks of 10
            const int row_b  = wid >> 2;        // 4 row blocks of 16

            ULL acc[4][5];
            #pragma unroll
            for (int ri = 0; ri < 4; ri++)
                #pragma unroll
                for (int i = 0; i < 5; i++) acc[ri][i] = 0ull;

            const float* pbase = sm + SM_PS + (row_b*16 + rowsub*4)*PSS;
            const float* vbase = sm + SM_V  + (oc_b*10 + ocsub*5)*VSS;

            #pragma unroll
            for (int phase = 0; phase < 2; phase++) {
                const int co = (l4 + 4*phase) * 42;     // chunk offset
                for (int j = 0; j < 20; j++) {
                    ULL p2[4];
                    #pragma unroll
                    for (int ri = 0; ri < 4; ri++)
                        p2[ri] = *(const ULL*)(pbase + ri*PSS + co + 2*j);
                    #pragma unroll
                    for (int i = 0; i < 5; i++) {
                        ULL v2 = *(const ULL*)(vbase + i*VSS + co + 2*j);
                        #pragma unroll
                        for (int ri = 0; ri < 4; ri++)
                            acc[ri][i] = ffma2(p2[ri], v2, acc[ri][i]);
                    }
                }
            }

            // reduce over 4 n-split lanes (xor 1,2 stays within (rowsub,ocsub) group)
            float red[4][5];
            #pragma unroll
            for (int ri = 0; ri < 4; ri++)
                #pragma unroll
                for (int i = 0; i < 5; i++) {
                    float lo, hi; upk2(acc[ri][i], lo, hi);
                    float a = lo + hi;
                    a += __shfl_xor_sync(0xffffffffu, a, 1);
                    a += __shfl_xor_sync(0xffffffffu, a, 2);
                    red[ri][i] = a;
                }
            const int c8 = oc_b*2 + ocsub;
            #pragma unroll
            for (int ri = 0; ri < 4; ri++) {
                if (l4 == ri) {
                    int row = row_b*16 + rowsub*4 + ri;   // tile-local; v=tile, w=row
                    float scale = rinv[row];
                    #pragma unroll
                    for (int i = 0; i < 5; i++) {
                        size_t idx = ((((size_t)b*40 + c8*5 + tile)*5 + i)*64 + h)*64 + row;
                        g_X[idx] += scale * red[ri][i];
                    }
                }
            }
        }
        __syncthreads();
    }
}

// ---------------- conv1: 2 h-columns per CTA, [64oc] x [40ci x 7kw], + ReLU ----------------
#define C1X 2880                              // Xs per h: [40][72]
#define C1_WS_OFF (2*C1X)                     // 5760
#define C1_SMEM_FLOATS (C1_WS_OFF + 280*66)   // 24240
#define C1_SMEM_BYTES  (C1_SMEM_FLOATS*4)

__global__ __launch_bounds__(512)
void conv1_kernel(const float* __restrict__ W1)
{
    extern __shared__ float sm[];
    float* Ws = sm + C1_WS_OFF;   // [(ci*7+kw)*66 + oc]
    const int d = blockIdx.y, b = blockIdx.z;
    const int t = threadIdx.x;
    const int hh   = t >> 8;          // which h within pair
    const int tl   = t & 255;
    const int lane = tl & 31;
    const int ocb  = (tl >> 5) * 8;
    const int h    = blockIdx.x*2 + hh;

    // zero pads for both halves
    for (int idx = t; idx < 480; idx += 512) {
        int g = idx / 240, k = idx % 240;
        int ci = k / 6, p = k % 6;
        sm[g*C1X + ci*72 + (p < 3 ? p : 64 + p)] = 0.f;
    }
    // fill X rows for both h
    for (int idx = t; idx < 5120; idx += 512) {
        int g = idx / 2560, k = idx % 2560;
        int ci = k >> 6, w = k & 63;
        int hg = blockIdx.x*2 + g;
        sm[g*C1X + ci*72 + 3 + w] = g_X[(((size_t)b*40 + ci)*5 + d)*4096 + hg*64 + w];
    }
    // weights (shared by both halves)
    for (int idx = t; idx < 64*280; idx += 512) {
        int oc = idx / 280, r = idx % 280;
        Ws[r*66 + oc] = W1[idx];
    }
    __syncthreads();

    float* Xs = sm + hh*C1X;
    ULL acc[4][2];
    #pragma unroll
    for (int i = 0; i < 4; i++) { acc[i][0] = 0ull; acc[i][1] = 0ull; }

    for (int ci = 0; ci < 40; ci++) {
        #pragma unroll
        for (int kw = 0; kw < 7; kw++) {
            float x0 = Xs[ci*72 + lane + kw];
            float x1 = Xs[ci*72 + 32 + lane + kw];
            ULL xx0 = pk2(x0, x0), xx1 = pk2(x1, x1);
            const float* wp = Ws + (ci*7+kw)*66 + ocb;
            #pragma unroll
            for (int i = 0; i < 4; i++) {
                ULL w2 = *(const ULL*)(wp + 2*i);
                acc[i][0] = ffma2(w2, xx0, acc[i][0]);
                acc[i][1] = ffma2(w2, xx1, acc[i][1]);
            }
        }
    }
    size_t obase = (((size_t)b*64 + ocb)*5 + d)*4096 + h*64;
    #pragma unroll
    for (int i = 0; i < 4; i++) {
        float a0lo, a0hi, a1lo, a1hi;
        upk2(acc[i][0], a0lo, a0hi);
        upk2(acc[i][1], a1lo, a1hi);
        size_t o0 = obase + (size_t)(2*i  )*5*4096;
        size_t o1 = obase + (size_t)(2*i+1)*5*4096;
        g_Y1[o0 + lane]      = fmaxf(a0lo, 0.f);
        g_Y1[o1 + lane]      = fmaxf(a0hi, 0.f);
        g_Y1[o0 + 32 + lane] = fmaxf(a1lo, 0.f);
        g_Y1[o1 + 32 + lane] = fmaxf(a1hi, 0.f);
    }
}

// ---------------- conv2: [64oc] x [64c x 7kd] over D(=5), + ReLU, 1024 threads ----------------
#define C2_WS_OFF 20480                       // Ys[64][5][64]
#define C2_SMEM_FLOATS (C2_WS_OFF + 448*65)
#define C2_SMEM_BYTES  (C2_SMEM_FLOATS*4)

__global__ __launch_bounds__(1024)
void conv2_kernel(const float* __restrict__ W2, float* __restrict__ out)
{
    extern __shared__ float sm[];
    float* Ys = sm;               // [(c*5+d)*64 + w]
    float* Ws = sm + C2_WS_OFF;   // [(c*7+kd)*65 + oc]
    const int h = blockIdx.x, b = blockIdx.y;
    const int t = threadIdx.x;
    const int oc = t >> 4, wg = t & 15;     // 4 w per thread

    for (int f = t; f < 5120; f += 1024) {
        int r = f >> 4, w4 = f & 15;
        int c = r / 5, d = r % 5;
        *(float4*)(Ys + r*64 + w4*4) =
            *(const float4*)(g_Y1 + (((size_t)b*64 + c)*5 + d)*4096 + h*64 + w4*4);
    }
    for (int idx = t; idx < 64*448; idx += 1024) {
        int o = idx / 448, r = idx % 448;
        Ws[r*65 + o] = W2[idx];
    }
    __syncthreads();

    ULL acc[5][2];
    #pragma unroll
    for (int d = 0; d < 5; d++) { acc[d][0] = 0ull; acc[d][1] = 0ull; }

    for (int c = 0; c < 64; c++) {
        ULL w2[7];
        #pragma unroll
        for (int kd = 0; kd < 7; kd++) {
            float wv = Ws[(c*7+kd)*65 + oc];
            w2[kd] = pk2(wv, wv);
        }
        #pragma unroll
        for (int dp = 0; dp < 5; dp++) {
            const float* yp = Ys + (c*5+dp)*64 + wg*4;
            ULL y20 = *(const ULL*)yp;
            ULL y21 = *(const ULL*)(yp + 2);
            #pragma unroll
            for (int d = 0; d < 5; d++) {
                int kd = dp - d + 3;
                if (kd < 0 || kd > 6) continue;     // compile-time pruned
                acc[d][0] = ffma2(w2[kd], y20, acc[d][0]);
                acc[d][1] = ffma2(w2[kd], y21, acc[d][1]);
            }
        }
    }
    #pragma unroll
    for (int d = 0; d < 5; d++) {
        size_t idx = (((size_t)b*64 + oc)*5 + d)*4096 + h*64 + wg*4;
        float lo0, hi0, lo1, hi1;
        upk2(acc[d][0], lo0, hi0);
        upk2(acc[d][1], lo1, hi1);
        *(float2*)(out + idx)     = make_float2(fmaxf(lo0, 0.f), fmaxf(hi0, 0.f));
        *(float2*)(out + idx + 2) = make_float2(fmaxf(lo1, 0.f), fmaxf(hi1, 0.f));
    }
}

// ---------------- launch ----------------
extern "C" void kernel_launch(void* const* d_in, const int* in_sizes, int n_in,
                              void* d_out, int out_size)
{
    const float* buffer = (const float*)d_in[0];
    const float* Wq = (const float*)d_in[1];
    const float* Wk = (const float*)d_in[2];
    const float* Wv = (const float*)d_in[3];
    const float* Wc = (const float*)d_in[4];
    const float* W1 = (const float*)d_in[5];
    const float* W2 = (const float*)d_in[6];
    float* out = (float*)d_out;

    cudaFuncSetAttribute(attn_kernel,  cudaFuncAttributeMaxDynamicSharedMemorySize, ATTN_SMEM_BYTES);
    cudaFuncSetAttribute(conv1_kernel, cudaFuncAttributeMaxDynamicSharedMemorySize, C1_SMEM_BYTES);
    cudaFuncSetAttribute(conv2_kernel, cudaFuncAttributeMaxDynamicSharedMemorySize, C2_SMEM_BYTES);

    attn_kernel <<<dim3(64, 8),     512, ATTN_SMEM_BYTES>>>(buffer, Wq, Wk, Wv, Wc);
    conv1_kernel<<<dim3(32, 5, 8),  512, C1_SMEM_BYTES>>>(W1);
    conv2_kernel<<<dim3(64, 8),    1024, C2_SMEM_BYTES>>>(W2, out);
}

// round 9
// speedup vs baseline: 1.6313x; 1.0169x over previous
#include <cuda_runtime.h>

typedef unsigned long long ULL;

// ---------------- f32x2 helpers ----------------
__device__ __forceinline__ ULL pk2(float lo, float hi) {
    ULL r; asm("mov.b64 %0, {%1, %2};" : "=l"(r) : "f"(lo), "f"(hi)); return r;
}
__device__ __forceinline__ void upk2(ULL v, float& lo, float& hi) {
    asm("mov.b64 {%0, %1}, %2;" : "=f"(lo), "=f"(hi) : "l"(v));
}
__device__ __forceinline__ ULL ffma2(ULL a, ULL b, ULL c) {
    ULL d; asm("fma.rn.f32x2 %0, %1, %2, %3;" : "=l"(d) : "l"(a), "l"(b), "l"(c));
    return d;
}
__device__ __forceinline__ int remap(int n) { return (n / 40) * 42 + (n % 40); }

// ---------------- scratch ----------------
__device__ float g_X [8*40*5*64*64];   // [b][c8*5+v][ar][h][w]
__device__ float g_Y1[8*64*5*64*64];   // [b][c][ar][h][w]

// ---------------- attn smem layout (floats) ----------------
#define PSS 334                  // P row stride: footprint 334; 4*PSS/2%16==12
#define VSS 338                  // V row stride: >=334; (5*VSS/2)%16==13
#define SM_PS   0                // Ps[64][334]=21376 ; Bs[64][320]=20480 overlays
#define SM_Q    21376            // Q[8][320] plain
#define SM_K    23936            // K[8][320] plain
#define SM_V    26496            // V[40][338] chunked = 13520
#define SM_WD   40016            // dup weights [c][96][2]=12288 (Phase A); stage[2][2560] overlays (Phase B)
#define SM_RINV 52304            // [2][64] double-buffered
#define ATTN_SMEM_FLOATS 52432
#define ATTN_SMEM_BYTES  (ATTN_SMEM_FLOATS*4)

__global__ __launch_bounds__(512)
void attn_kernel(const float* __restrict__ buffer,
                 const float* __restrict__ Wq, const float* __restrict__ Wk,
                 const float* __restrict__ Wv, const float* __restrict__ Wc)
{
    extern __shared__ float sm[];
    float* Bs = sm;              // Phase A input, overlaid by Ps afterwards

    const int h    = blockIdx.x;
    const int b    = blockIdx.y;
    const int t    = threadIdx.x;
    const int lane = t & 31;
    const int wid  = t >> 5;     // 16 warps

    // ---- weights -> smem, duplicated into f32x2 pairs ----
    for (int idx = t; idx < 96*64; idx += 512) {
        int oc = idx >> 6, c = idx & 63;
        float v;
        if      (oc <  8) v = Wq[(oc      )*64 + c];
        else if (oc < 16) v = Wk[(oc -  8)*64 + c];
        else if (oc < 56) v = Wv[(oc - 16)*64 + c];
        else              v = Wc[(oc - 56)*64 + c];
        sm[SM_WD + c*192 + oc*2    ] = v;
        sm[SM_WD + c*192 + oc*2 + 1] = v;
    }
    // ---- buffer slice Bs[c][v*64+w] ----
    for (int f = t; f < 5120; f += 512) {
        int r  = f >> 4;
        int w4 = f & 15;
        int c = r / 5, v = r % 5;
        float4 val = *(const float4*)(buffer + (((size_t)(b*64 + c)*5 + v)*4096 + h*64 + w4*4));
        *(float4*)(Bs + c*320 + v*64 + w4*4) = val;
    }
    __syncthreads();

    // ---- Phase A: [96oc x 64c] x [64c x 320n], 6 oc per warp ----
    {
        const int ocb = wid * 6;
        ULL acc[6][5];
        #pragma unroll
        for (int i = 0; i < 6; i++)
            #pragma unroll
            for (int jp = 0; jp < 5; jp++) acc[i][jp] = 0ull;

        for (int c = 0; c < 64; c++) {
            ULL w2[6];
            #pragma unroll
            for (int i = 0; i < 6; i++)
                w2[i] = *(const ULL*)(sm + SM_WD + c*192 + (ocb + i)*2);
            #pragma unroll
            for (int jp = 0; jp < 5; jp++) {
                ULL b2 = *(const ULL*)(Bs + c*320 + 2*lane + 64*jp);
                #pragma unroll
                for (int i = 0; i < 6; i++) acc[i][jp] = ffma2(w2[i], b2, acc[i][jp]);
            }
        }
        #pragma unroll
        for (int i = 0; i < 6; i++) {
            int oc = ocb + i;
            #pragma unroll
            for (int jp = 0; jp < 5; jp++) {
                int n = 2*lane + 64*jp;
                if (oc < 8)       *(ULL*)(sm + SM_Q + oc*320 + n)              = acc[i][jp];
                else if (oc < 16) *(ULL*)(sm + SM_K + (oc-8)*320 + n)          = acc[i][jp];
                else if (oc < 56) *(ULL*)(sm + SM_V + (oc-16)*VSS + remap(n))  = acc[i][jp];
                else {
                    int cc = oc - 56;          // c8*5 + ar
                    int c8 = cc / 5, ar = cc % 5;
                    float lo, hi; upk2(acc[i][jp], lo, hi);
                    size_t idx = ((((size_t)b*40 + c8*5 + jp)*5 + ar)*64 + h)*64 + 2*lane;
                    *(float2*)(g_X + idx) = make_float2(lo, hi);
                }
            }
        }
    }
    __syncthreads();

    // ---- Phase B: 5 tiles of 64 rows ----
    for (int tile = 0; tile < 5; tile++) {
        const int m0 = tile * 64;
        float* rinv = sm + SM_RINV + (tile & 1)*64;
        float* stg  = sm + SM_WD   + (tile & 1)*2560;   // stage[row64][oc40]

        // B1: scores (scalar, inner dim 8) + softmax -> Ps (chunked), rinv. 4 rows/warp.
        {
            float q[4][8];
            #pragma unroll
            for (int mi = 0; mi < 4; mi++)
                #pragma unroll
                for (int d = 0; d < 8; d++)
                    q[mi][d] = sm[SM_Q + d*320 + m0 + wid*4 + mi];

            float s[4][10];
            #pragma unroll
            for (int j = 0; j < 10; j++) {
                int n = lane + 32*j;
                float kv[8];
                #pragma unroll
                for (int d = 0; d < 8; d++) kv[d] = sm[SM_K + d*320 + n];
                #pragma unroll
                for (int mi = 0; mi < 4; mi++) {
                    float a = 0.f;
                    #pragma unroll
                    for (int d = 0; d < 8; d++) a += q[mi][d]*kv[d];
                    s[mi][j] = a;
                }
            }
            #pragma unroll
            for (int mi = 0; mi < 4; mi++) {
                float mx = s[mi][0];
                #pragma unroll
                for (int j = 1; j < 10; j++) mx = fmaxf(mx, s[mi][j]);
                #pragma unroll
                for (int o = 16; o; o >>= 1) mx = fmaxf(mx, __shfl_xor_sync(0xffffffffu, mx, o));
                float sum = 0.f;
                int r = wid*4 + mi;
                #pragma unroll
                for (int j = 0; j < 10; j++) {
                    float e = __expf(s[mi][j] - mx);
                    sum += e;
                    sm[SM_PS + r*PSS + remap(lane + 32*j)] = e;
                }
                #pragma unroll
                for (int o = 16; o; o >>= 1) sum += __shfl_xor_sync(0xffffffffu, sum, o);
                if (lane == 0) rinv[r] = 1.0f / sum;
            }
        }
        __syncthreads();

        // B2: O[64][40] = P[64][320] * V^T
        // warp tile: 16 rows x 20 ocs; thread: 4 rows x 5 ocs
        // n-split: l2 (in-warp, 2) x ws (warp pairs, 2) -> stage combine
        {
            const int l2     = lane & 1;        // in-warp n-split
            const int ocsub  = (lane >> 1) & 3; // 4 oc sub-blocks of 5
            const int rowsub = lane >> 3;       // 4 row sub-blocks of 4
            const int ws     = wid & 1;         // cross-warp n-split
            const int oc_b   = (wid >> 1) & 1;  // 2 oc blocks of 20
            const int row_b  = wid >> 2;        // 4 row blocks of 16

            ULL acc[4][5];
            #pragma unroll
            for (int ri = 0; ri < 4; ri++)
                #pragma unroll
                for (int i = 0; i < 5; i++) acc[ri][i] = 0ull;

            const float* pbase = sm + SM_PS + (row_b*16 + rowsub*4)*PSS;
            const float* vbase = sm + SM_V  + (oc_b*20 + ocsub*5)*VSS;

            #pragma unroll
            for (int phase = 0; phase < 2; phase++) {
                const int co = (l2 + 2*ws + 4*phase) * 42;     // chunk offset
                for (int j = 0; j < 20; j++) {
                    ULL p2[4];
                    #pragma unroll
                    for (int ri = 0; ri < 4; ri++)
                        p2[ri] = *(const ULL*)(pbase + ri*PSS + co + 2*j);
                    #pragma unroll
                    for (int i = 0; i < 5; i++) {
                        ULL v2 = *(const ULL*)(vbase + i*VSS + co + 2*j);
                        #pragma unroll
                        for (int ri = 0; ri < 4; ri++)
                            acc[ri][i] = ffma2(p2[ri], v2, acc[ri][i]);
                    }
                }
            }

            // reduce in-warp l2 pair (xor 1)
            float red[4][5];
            #pragma unroll
            for (int ri = 0; ri < 4; ri++)
                #pragma unroll
                for (int i = 0; i < 5; i++) {
                    float lo, hi; upk2(acc[ri][i], lo, hi);
                    float a = lo + hi;
                    a += __shfl_xor_sync(0xffffffffu, a, 1);
                    red[ri][i] = a;
                }

            const int ocbase = oc_b*20 + ocsub*5;
            if (ws == 0) {
                #pragma unroll
                for (int rr = 0; rr < 2; rr++) {
                    int ri  = l2*2 + rr;
                    int row = row_b*16 + rowsub*4 + ri;
                    #pragma unroll
                    for (int i = 0; i < 5; i++)
                        stg[row*40 + ocbase + i] = red[ri][i];
                }
            }
            __syncthreads();
            if (ws == 1) {
                #pragma unroll
                for (int rr = 0; rr < 2; rr++) {
                    int ri  = l2*2 + rr;
                    int row = row_b*16 + rowsub*4 + ri;   // tile-local; v=tile, w=row
                    float scale = rinv[row];
                    #pragma unroll
                    for (int i = 0; i < 5; i++) {
                        float val = red[ri][i] + stg[row*40 + ocbase + i];
                        int c8 = (ocbase + i) / 5, ar = (ocbase + i) % 5;
                        size_t idx = ((((size_t)b*40 + c8*5 + tile)*5 + ar)*64 + h)*64 + row;
                        g_X[idx] += scale * val;
                    }
                }
            }
        }
        // no further sync needed: next B1 writes Ps/rinv[other parity]; ws==1
        // warps finish g_X before arriving at next tile's post-B1 barrier.
    }
}

// ---------------- conv1: 2 h-columns per CTA, [64oc] x [40ci x 7kw], + ReLU ----------------
#define C1X 2880                              // Xs per h: [40][72]
#define C1_WS_OFF (2*C1X)                     // 5760
#define C1_SMEM_FLOATS (C1_WS_OFF + 280*66)   // 24240
#define C1_SMEM_BYTES  (C1_SMEM_FLOATS*4)

__global__ __launch_bounds__(512)
void conv1_kernel(const float* __restrict__ W1)
{
    extern __shared__ float sm[];
    float* Ws = sm + C1_WS_OFF;   // [(ci*7+kw)*66 + oc]
    const int d = blockIdx.y, b = blockIdx.z;
    const int t = threadIdx.x;
    const int hh   = t >> 8;          // which h within pair
    const int tl   = t & 255;
    const int lane = tl & 31;
    const int ocb  = (tl >> 5) * 8;
    const int h    = blockIdx.x*2 + hh;

    // zero pads for both halves
    for (int idx = t; idx < 480; idx += 512) {
        int g = idx / 240, k = idx % 240;
        int ci = k / 6, p = k % 6;
        sm[g*C1X + ci*72 + (p < 3 ? p : 64 + p)] = 0.f;
    }
    // fill X rows for both h
    for (int idx = t; idx < 5120; idx += 512) {
        int g = idx / 2560, k = idx % 2560;
        int ci = k >> 6, w = k & 63;
        int hg = blockIdx.x*2 + g;
        sm[g*C1X + ci*72 + 3 + w] = g_X[(((size_t)b*40 + ci)*5 + d)*4096 + hg*64 + w];
    }
    // weights (shared by both halves)
    for (int idx = t; idx < 64*280; idx += 512) {
        int oc = idx / 280, r = idx % 280;
        Ws[r*66 + oc] = W1[idx];
    }
    __syncthreads();

    float* Xs = sm + hh*C1X;
    ULL acc[4][2];
    #pragma unroll
    for (int i = 0; i < 4; i++) { acc[i][0] = 0ull; acc[i][1] = 0ull; }

    for (int ci = 0; ci < 40; ci++) {
        #pragma unroll
        for (int kw = 0; kw < 7; kw++) {
            float x0 = Xs[ci*72 + lane + kw];
            float x1 = Xs[ci*72 + 32 + lane + kw];
            ULL xx0 = pk2(x0, x0), xx1 = pk2(x1, x1);
            const float* wp = Ws + (ci*7+kw)*66 + ocb;
            #pragma unroll
            for (int i = 0; i < 4; i++) {
                ULL w2 = *(const ULL*)(wp + 2*i);
                acc[i][0] = ffma2(w2, xx0, acc[i][0]);
                acc[i][1] = ffma2(w2, xx1, acc[i][1]);
            }
        }
    }
    size_t obase = (((size_t)b*64 + ocb)*5 + d)*4096 + h*64;
    #pragma unroll
    for (int i = 0; i < 4; i++) {
        float a0lo, a0hi, a1lo, a1hi;
        upk2(acc[i][0], a0lo, a0hi);
        upk2(acc[i][1], a1lo, a1hi);
        size_t o0 = obase + (size_t)(2*i  )*5*4096;
        size_t o1 = obase + (size_t)(2*i+1)*5*4096;
        g_Y1[o0 + lane]      = fmaxf(a0lo, 0.f);
        g_Y1[o1 + lane]      = fmaxf(a0hi, 0.f);
        g_Y1[o0 + 32 + lane] = fmaxf(a1lo, 0.f);
        g_Y1[o1 + 32 + lane] = fmaxf(a1hi, 0.f);
    }
}

// ---------------- conv2: [64oc] x [64c x 7kd] over D(=5), + ReLU, 1024 threads ----------------
#define C2_WS_OFF 20480                       // Ys[64][5][64]
#define C2_SMEM_FLOATS (C2_WS_OFF + 448*65)
#define C2_SMEM_BYTES  (C2_SMEM_FLOATS*4)

__global__ __launch_bounds__(1024)
void conv2_kernel(const float* __restrict__ W2, float* __restrict__ out)
{
    extern __shared__ float sm[];
    float* Ys = sm;               // [(c*5+d)*64 + w]
    float* Ws = sm + C2_WS_OFF;   // [(c*7+kd)*65 + oc]
    const int h = blockIdx.x, b = blockIdx.y;
    const int t = threadIdx.x;
    const int oc = t >> 4, wg = t & 15;     // 4 w per thread

    for (int f = t; f < 5120; f += 1024) {
        int r = f >> 4, w4 = f & 15;
        int c = r / 5, d = r % 5;
        *(float4*)(Ys + r*64 + w4*4) =
            *(const float4*)(g_Y1 + (((size_t)b*64 + c)*5 + d)*4096 + h*64 + w4*4);
    }
    for (int idx = t; idx < 64*448; idx += 1024) {
        int o = idx / 448, r = idx % 448;
        Ws[r*65 + o] = W2[idx];
    }
    __syncthreads();

    ULL acc[5][2];
    #pragma unroll
    for (int d = 0; d < 5; d++) { acc[d][0] = 0ull; acc[d][1] = 0ull; }

    for (int c = 0; c < 64; c++) {
        ULL w2[7];
        #pragma unroll
        for (int kd = 0; kd < 7; kd++) {
            float wv = Ws[(c*7+kd)*65 + oc];
            w2[kd] = pk2(wv, wv);
        }
        #pragma unroll
        for (int dp = 0; dp < 5; dp++) {
            const float* yp = Ys + (c*5+dp)*64 + wg*4;
            ULL y20 = *(const ULL*)yp;
            ULL y21 = *(const ULL*)(yp + 2);
            #pragma unroll
            for (int d = 0; d < 5; d++) {
                int kd = dp - d + 3;
                if (kd < 0 || kd > 6) continue;     // compile-time pruned
                acc[d][0] = ffma2(w2[kd], y20, acc[d][0]);
                acc[d][1] = ffma2(w2[kd], y21, acc[d][1]);
            }
        }
    }
    #pragma unroll
    for (int d = 0; d < 5; d++) {
        size_t idx = (((size_t)b*64 + oc)*5 + d)*4096 + h*64 + wg*4;
        float lo0, hi0, lo1, hi1;
        upk2(acc[d][0], lo0, hi0);
        upk2(acc[d][1], lo1, hi1);
        *(float2*)(out + idx)     = make_float2(fmaxf(lo0, 0.f), fmaxf(hi0, 0.f));
        *(float2*)(out + idx + 2) = make_float2(fmaxf(lo1, 0.f), fmaxf(hi1, 0.f));
    }
}

// ---------------- launch ----------------
extern "C" void kernel_launch(void* const* d_in, const int* in_sizes, int n_in,
                              void* d_out, int out_size)
{
    const float* buffer = (const float*)d_in[0];
    const float* Wq = (const float*)d_in[1];
    const float* Wk = (const float*)d_in[2];
    const float* Wv = (const float*)d_in[3];
    const float* Wc = (const float*)d_in[4];
    const float* W1 = (const float*)d_in[5];
    const float* W2 = (const float*)d_in[6];
    float* out = (float*)d_out;

    cudaFuncSetAttribute(attn_kernel,  cudaFuncAttributeMaxDynamicSharedMemorySize, ATTN_SMEM_BYTES);
    cudaFuncSetAttribute(conv1_kernel, cudaFuncAttributeMaxDynamicSharedMemorySize, C1_SMEM_BYTES);
    cudaFuncSetAttribute(conv2_kernel, cudaFuncAttributeMaxDynamicSharedMemorySize, C2_SMEM_BYTES);

    attn_kernel <<<dim3(64, 8),     512, ATTN_SMEM_BYTES>>>(buffer, Wq, Wk, Wv, Wc);
    conv1_kernel<<<dim3(32, 5, 8),  512, C1_SMEM_BYTES>>>(W1);
    conv2_kernel<<<dim3(64, 8),    1024, C2_SMEM_BYTES>>>(W2, out);
}

// round 10
// speedup vs baseline: 1.6555x; 1.0148x over previous
#include <cuda_runtime.h>

typedef unsigned long long ULL;

// ---------------- f32x2 helpers ----------------
__device__ __forceinline__ ULL pk2(float lo, float hi) {
    ULL r; asm("mov.b64 %0, {%1, %2};" : "=l"(r) : "f"(lo), "f"(hi)); return r;
}
__device__ __forceinline__ void upk2(ULL v, float& lo, float& hi) {
    asm("mov.b64 {%0, %1}, %2;" : "=f"(lo), "=f"(hi) : "l"(v));
}
__device__ __forceinline__ ULL ffma2(ULL a, ULL b, ULL c) {
    ULL d; asm("fma.rn.f32x2 %0, %1, %2, %3;" : "=l"(d) : "l"(a), "l"(b), "l"(c));
    return d;
}
__device__ __forceinline__ int remap48(int n) { return (n / 40) * 48 + (n % 40); }

// ---------------- scratch ----------------
__device__ float g_X [8*40*5*64*64];   // [b][c8*5+v][ar][h][w]
__device__ float g_Y1[8*64*5*64*64];   // [b][c][ar][h][w]

// ---------------- attn smem layout (floats) ----------------
#define PSS 388                  // P row stride: 388%32==4 (rowsub bijection), mult of 4, >=376
#define VSS 404                  // V row stride: (5*404)%32==4 (ocsub bijection), mult of 4, >=376
#define SM_PS   0                // Ps[64][388]=24832 ; Bs[64][320]=20480 overlays
#define SM_Q    24832            // Q[8][320] plain
#define SM_K    27392            // K[8][320] plain
#define SM_V    29952            // V[40][404] chunk48 = 16160
#define SM_W    46112            // Wsm[c][96]=6144 (Phase A); stage[2][2560] overlays (Phase B)
#define SM_RINV 52256            // [2][64] double-buffered
#define ATTN_SMEM_FLOATS 52384
#define ATTN_SMEM_BYTES  (ATTN_SMEM_FLOATS*4)

__global__ __launch_bounds__(512)
void attn_kernel(const float* __restrict__ buffer,
                 const float* __restrict__ Wq, const float* __restrict__ Wk,
                 const float* __restrict__ Wv, const float* __restrict__ Wc)
{
    extern __shared__ float sm[];
    float* Bs  = sm;             // Phase A input, overlaid by Ps afterwards
    float* Wsm = sm + SM_W;      // [c][96]

    const int h    = blockIdx.x;
    const int b    = blockIdx.y;
    const int t    = threadIdx.x;
    const int lane = t & 31;
    const int wid  = t >> 5;     // 16 warps

    // ---- weights -> smem (transposed, unduplicated) ----
    for (int idx = t; idx < 96*64; idx += 512) {
        int oc = idx >> 6, c = idx & 63;
        float v;
        if      (oc <  8) v = Wq[(oc      )*64 + c];
        else if (oc < 16) v = Wk[(oc -  8)*64 + c];
        else if (oc < 56) v = Wv[(oc - 16)*64 + c];
        else              v = Wc[(oc - 56)*64 + c];
        Wsm[c*96 + oc] = v;
    }
    // ---- buffer slice Bs[c][v*64+w] ----
    for (int f = t; f < 5120; f += 512) {
        int r  = f >> 4;
        int w4 = f & 15;
        int c = r / 5, v = r % 5;
        float4 val = *(const float4*)(buffer + (((size_t)(b*64 + c)*5 + v)*4096 + h*64 + w4*4));
        *(float4*)(Bs + c*320 + v*64 + w4*4) = val;
    }
    __syncthreads();

    // ---- Phase A: [96oc x 64c] x [64c x 320n], 6 oc per warp ----
    {
        const int ocb = wid * 6;
        ULL acc[6][5];
        #pragma unroll
        for (int i = 0; i < 6; i++)
            #pragma unroll
            for (int jp = 0; jp < 5; jp++) acc[i][jp] = 0ull;

        for (int c = 0; c < 64; c++) {
            ULL w2[6];
            #pragma unroll
            for (int i = 0; i < 6; i++) {
                float wv = Wsm[c*96 + ocb + i];
                w2[i] = pk2(wv, wv);
            }
            #pragma unroll
            for (int jp = 0; jp < 5; jp++) {
                ULL b2 = *(const ULL*)(Bs + c*320 + 2*lane + 64*jp);
                #pragma unroll
                for (int i = 0; i < 6; i++) acc[i][jp] = ffma2(w2[i], b2, acc[i][jp]);
            }
        }
        #pragma unroll
        for (int i = 0; i < 6; i++) {
            int oc = ocb + i;
            #pragma unroll
            for (int jp = 0; jp < 5; jp++) {
                int n = 2*lane + 64*jp;
                if (oc < 8)       *(ULL*)(sm + SM_Q + oc*320 + n)               = acc[i][jp];
                else if (oc < 16) *(ULL*)(sm + SM_K + (oc-8)*320 + n)           = acc[i][jp];
                else if (oc < 56) *(ULL*)(sm + SM_V + (oc-16)*VSS + remap48(n)) = acc[i][jp];
                else {
                    int cc = oc - 56;          // c8*5 + ar
                    int c8 = cc / 5, ar = cc % 5;
                    float lo, hi; upk2(acc[i][jp], lo, hi);
                    size_t idx = ((((size_t)b*40 + c8*5 + jp)*5 + ar)*64 + h)*64 + 2*lane;
                    *(float2*)(g_X + idx) = make_float2(lo, hi);
                }
            }
        }
    }
    __syncthreads();

    // ---- Phase B: 5 tiles of 64 rows ----
    for (int tile = 0; tile < 5; tile++) {
        const int m0 = tile * 64;
        float* rinv = sm + SM_RINV + (tile & 1)*64;
        float* stg  = sm + SM_W    + (tile & 1)*2560;   // stage[row64][oc40]

        // B1: scores (scalar, inner dim 8) + softmax -> Ps (chunk48), rinv. 4 rows/warp.
        {
            float q[4][8];
            #pragma unroll
            for (int mi = 0; mi < 4; mi++)
                #pragma unroll
                for (int d = 0; d < 8; d++)
                    q[mi][d] = sm[SM_Q + d*320 + m0 + wid*4 + mi];

            float s[4][10];
            #pragma unroll
            for (int j = 0; j < 10; j++) {
                int n = lane + 32*j;
                float kv[8];
                #pragma unroll
                for (int d = 0; d < 8; d++) kv[d] = sm[SM_K + d*320 + n];
                #pragma unroll
                for (int mi = 0; mi < 4; mi++) {
                    float a = 0.f;
                    #pragma unroll
                    for (int d = 0; d < 8; d++) a += q[mi][d]*kv[d];
                    s[mi][j] = a;
                }
            }
            #pragma unroll
            for (int mi = 0; mi < 4; mi++) {
                float mx = s[mi][0];
                #pragma unroll
                for (int j = 1; j < 10; j++) mx = fmaxf(mx, s[mi][j]);
                #pragma unroll
                for (int o = 16; o; o >>= 1) mx = fmaxf(mx, __shfl_xor_sync(0xffffffffu, mx, o));
                float sum = 0.f;
                int r = wid*4 + mi;
                #pragma unroll
                for (int j = 0; j < 10; j++) {
                    float e = __expf(s[mi][j] - mx);
                    sum += e;
                    sm[SM_PS + r*PSS + remap48(lane + 32*j)] = e;
                }
                #pragma unroll
                for (int o = 16; o; o >>= 1) sum += __shfl_xor_sync(0xffffffffu, sum, o);
                if (lane == 0) rinv[r] = 1.0f / sum;
            }
        }
        __syncthreads();

        // B2: O[64][40] = P[64][320] * V^T  — LDS.128 hot loop
        // warp tile: 16 rows x 20 ocs; thread: 4 rows (interleaved ri*4+rowsub) x 5 ocs
        // n-split: l2 (in-warp, 2) x ws (warp pairs, 2) -> stage combine
        {
            const int l2     = lane & 1;        // in-warp n-split
            const int ocsub  = (lane >> 1) & 3; // 4 oc sub-blocks of 5
            const int rowsub = lane >> 3;       // row within group of 4
            const int ws     = wid & 1;         // cross-warp n-split
            const int oc_b   = (wid >> 1) & 1;  // 2 oc blocks of 20
            const int row_b  = wid >> 2;        // 4 row blocks of 16

            ULL acc[4][5];
            #pragma unroll
            for (int ri = 0; ri < 4; ri++)
                #pragma unroll
                for (int i = 0; i < 5; i++) acc[ri][i] = 0ull;

            const float* pbase = sm + SM_PS + (row_b*16 + rowsub)*PSS;  // + ri*4*PSS per ri
            const float* vbase = sm + SM_V  + (oc_b*20 + ocsub*5)*VSS;

            #pragma unroll
            for (int phase = 0; phase < 2; phase++) {
                const int co = (l2 + 2*ws + 4*phase) * 48;     // chunk offset
                for (int jq = 0; jq < 10; jq++) {
                    ULL p2[4][2];
                    #pragma unroll
                    for (int ri = 0; ri < 4; ri++) {
                        ulonglong2 tp = *(const ulonglong2*)(pbase + ri*4*PSS + co + 4*jq);
                        p2[ri][0] = tp.x; p2[ri][1] = tp.y;
                    }
                    #pragma unroll
                    for (int i = 0; i < 5; i++) {
                        ulonglong2 tv = *(const ulonglong2*)(vbase + i*VSS + co + 4*jq);
                        #pragma unroll
                        for (int ri = 0; ri < 4; ri++) {
                            acc[ri][i] = ffma2(p2[ri][0], tv.x, acc[ri][i]);
                            acc[ri][i] = ffma2(p2[ri][1], tv.y, acc[ri][i]);
                        }
                    }
                }
            }

            // reduce in-warp l2 pair (xor 1)
            float red[4][5];
            #pragma unroll
            for (int ri = 0; ri < 4; ri++)
                #pragma unroll
                for (int i = 0; i < 5; i++) {
                    float lo, hi; upk2(acc[ri][i], lo, hi);
                    float a = lo + hi;
                    a += __shfl_xor_sync(0xffffffffu, a, 1);
                    red[ri][i] = a;
                }

            const int ocbase = oc_b*20 + ocsub*5;
            if (ws == 0) {
                #pragma unroll
                for (int rr = 0; rr < 2; rr++) {
                    int ri  = l2*2 + rr;
                    int row = row_b*16 + ri*4 + rowsub;
                    #pragma unroll
                    for (int i = 0; i < 5; i++)
                        stg[row*40 + ocbase + i] = red[ri][i];
                }
            }
            __syncthreads();
            if (ws == 1) {
                #pragma unroll
                for (int rr = 0; rr < 2; rr++) {
                    int ri  = l2*2 + rr;
                    int row = row_b*16 + ri*4 + rowsub;   // tile-local; v=tile, w=row
                    float scale = rinv[row];
                    #pragma unroll
                    for (int i = 0; i < 5; i++) {
                        float val = red[ri][i] + stg[row*40 + ocbase + i];
                        int c8 = (ocbase + i) / 5, ar = (ocbase + i) % 5;
                        size_t idx = ((((size_t)b*40 + c8*5 + tile)*5 + ar)*64 + h)*64 + row;
                        g_X[idx] += scale * val;
                    }
                }
            }
        }
        // next B1 writes Ps only after the in-B2 barrier; rinv/stage parity-buffered.
    }
}

// ---------------- conv1: 2 h-columns per CTA, [64oc] x [40ci x 7kw], + ReLU ----------------
#define C1X 2880                              // Xs per h: [40][72]
#define C1_WS_OFF (2*C1X)                     // 5760
#define C1_SMEM_FLOATS (C1_WS_OFF + 280*66)   // 24240
#define C1_SMEM_BYTES  (C1_SMEM_FLOATS*4)

__global__ __launch_bounds__(512)
void conv1_kernel(const float* __restrict__ W1)
{
    extern __shared__ float sm[];
    float* Ws = sm + C1_WS_OFF;   // [(ci*7+kw)*66 + oc]
    const int d = blockIdx.y, b = blockIdx.z;
    const int t = threadIdx.x;
    const int hh   = t >> 8;          // which h within pair
    const int tl   = t & 255;
    const int lane = tl & 31;
    const int ocb  = (tl >> 5) * 8;
    const int h    = blockIdx.x*2 + hh;

    // zero pads for both halves
    for (int idx = t; idx < 480; idx += 512) {
        int g = idx / 240, k = idx % 240;
        int ci = k / 6, p = k % 6;
        sm[g*C1X + ci*72 + (p < 3 ? p : 64 + p)] = 0.f;
    }
    // fill X rows for both h
    for (int idx = t; idx < 5120; idx += 512) {
        int g = idx / 2560, k = idx % 2560;
        int ci = k >> 6, w = k & 63;
        int hg = blockIdx.x*2 + g;
        sm[g*C1X + ci*72 + 3 + w] = g_X[(((size_t)b*40 + ci)*5 + d)*4096 + hg*64 + w];
    }
    // weights (shared by both halves)
    for (int idx = t; idx < 64*280; idx += 512) {
        int oc = idx / 280, r = idx % 280;
        Ws[r*66 + oc] = W1[idx];
    }
    __syncthreads();

    float* Xs = sm + hh*C1X;
    ULL acc[4][2];
    #pragma unroll
    for (int i = 0; i < 4; i++) { acc[i][0] = 0ull; acc[i][1] = 0ull; }

    for (int ci = 0; ci < 40; ci++) {
        #pragma unroll
        for (int kw = 0; kw < 7; kw++) {
            float x0 = Xs[ci*72 + lane + kw];
            float x1 = Xs[ci*72 + 32 + lane + kw];
            ULL xx0 = pk2(x0, x0), xx1 = pk2(x1, x1);
            const float* wp = Ws + (ci*7+kw)*66 + ocb;
            #pragma unroll
            for (int i = 0; i < 4; i++) {
                ULL w2 = *(const ULL*)(wp + 2*i);
                acc[i][0] = ffma2(w2, xx0, acc[i][0]);
                acc[i][1] = ffma2(w2, xx1, acc[i][1]);
            }
        }
    }
    size_t obase = (((size_t)b*64 + ocb)*5 + d)*4096 + h*64;
    #pragma unroll
    for (int i = 0; i < 4; i++) {
        float a0lo, a0hi, a1lo, a1hi;
        upk2(acc[i][0], a0lo, a0hi);
        upk2(acc[i][1], a1lo, a1hi);
        size_t o0 = obase + (size_t)(2*i  )*5*4096;
        size_t o1 = obase + (size_t)(2*i+1)*5*4096;
        g_Y1[o0 + lane]      = fmaxf(a0lo, 0.f);
        g_Y1[o1 + lane]      = fmaxf(a0hi, 0.f);
        g_Y1[o0 + 32 + lane] = fmaxf(a1lo, 0.f);
        g_Y1[o1 + 32 + lane] = fmaxf(a1hi, 0.f);
    }
}

// ---------------- conv2: [64oc] x [64c x 7kd] over D(=5), + ReLU, 1024 threads ----------------
#define C2_WS_OFF 20480                       // Ys[64][5][64]
#define C2_SMEM_FLOATS (C2_WS_OFF + 448*65)
#define C2_SMEM_BYTES  (C2_SMEM_FLOATS*4)

__global__ __launch_bounds__(1024)
void conv2_kernel(const float* __restrict__ W2, float* __restrict__ out)
{
    extern __shared__ float sm[];
    float* Ys = sm;               // [(c*5+d)*64 + w]
    float* Ws = sm + C2_WS_OFF;   // [(c*7+kd)*65 + oc]
    const int h = blockIdx.x, b = blockIdx.y;
    const int t = threadIdx.x;
    const int oc = t >> 4, wg = t & 15;     // 4 w per thread

    for (int f = t; f < 5120; f += 1024) {
        int r = f >> 4, w4 = f & 15;
        int c = r / 5, d = r % 5;
        *(float4*)(Ys + r*64 + w4*4) =
            *(const float4*)(g_Y1 + (((size_t)b*64 + c)*5 + d)*4096 + h*64 + w4*4);
    }
    for (int idx = t; idx < 64*448; idx += 1024) {
        int o = idx / 448, r = idx % 448;
        Ws[r*65 + o] = W2[idx];
    }
    __syncthreads();

    ULL acc[5][2];
    #pragma unroll
    for (int d = 0; d < 5; d++) { acc[d][0] = 0ull; acc[d][1] = 0ull; }

    for (int c = 0; c < 64; c++) {
        ULL w2[7];
        #pragma unroll
        for (int kd = 0; kd < 7; kd++) {
            float wv = Ws[(c*7+kd)*65 + oc];
            w2[kd] = pk2(wv, wv);
        }
        #pragma unroll
        for (int dp = 0; dp < 5; dp++) {
            const float* yp = Ys + (c*5+dp)*64 + wg*4;
            ULL y20 = *(const ULL*)yp;
            ULL y21 = *(const ULL*)(yp + 2);
            #pragma unroll
            for (int d = 0; d < 5; d++) {
                int kd = dp - d + 3;
                if (kd < 0 || kd > 6) continue;     // compile-time pruned
                acc[d][0] = ffma2(w2[kd], y20, acc[d][0]);
                acc[d][1] = ffma2(w2[kd], y21, acc[d][1]);
            }
        }
    }
    #pragma unroll
    for (int d = 0; d < 5; d++) {
        size_t idx = (((size_t)b*64 + oc)*5 + d)*4096 + h*64 + wg*4;
        float lo0, hi0, lo1, hi1;
        upk2(acc[d][0], lo0, hi0);
        upk2(acc[d][1], lo1, hi1);
        *(float2*)(out + idx)     = make_float2(fmaxf(lo0, 0.f), fmaxf(hi0, 0.f));
        *(float2*)(out + idx + 2) = make_float2(fmaxf(lo1, 0.f), fmaxf(hi1, 0.f));
    }
}

// ---------------- launch ----------------
extern "C" void kernel_launch(void* const* d_in, const int* in_sizes, int n_in,
                              void* d_out, int out_size)
{
    const float* buffer = (const float*)d_in[0];
    const float* Wq = (const float*)d_in[1];
    const float* Wk = (const float*)d_in[2];
    const float* Wv = (const float*)d_in[3];
    const float* Wc = (const float*)d_in[4];
    const float* W1 = (const float*)d_in[5];
    const float* W2 = (const float*)d_in[6];
    float* out = (float*)d_out;

    cudaFuncSetAttribute(attn_kernel,  cudaFuncAttributeMaxDynamicSharedMemorySize, ATTN_SMEM_BYTES);
    cudaFuncSetAttribute(conv1_kernel, cudaFuncAttributeMaxDynamicSharedMemorySize, C1_SMEM_BYTES);
    cudaFuncSetAttribute(conv2_kernel, cudaFuncAttributeMaxDynamicSharedMemorySize, C2_SMEM_BYTES);

    attn_kernel <<<dim3(64, 8),     512, ATTN_SMEM_BYTES>>>(buffer, Wq, Wk, Wv, Wc);
    conv1_kernel<<<dim3(32, 5, 8),  512, C1_SMEM_BYTES>>>(W1);
    conv2_kernel<<<dim3(64, 8),    1024, C2_SMEM_BYTES>>>(W2, out);
}